// round 12
// baseline (speedup 1.0000x reference)
#include <cuda_runtime.h>
#include <cuda_fp16.h>
#include <cstdint>
#include <cstddef>

#define NB     4
#define NSEQ   4096
#define EDIM   128
#define FFD    512
#define NTOK   (NB * NSEQ)

// ---------------- scratch ----------------
__device__ float  g_h   [NTOK * EDIM];
__device__ float  g_S   [NTOK * EDIM];
__device__ __half g_Xh  [NTOK * 256];
__device__ __half g_atth[NTOK * EDIM];
__device__ float  g_out1[NTOK * EDIM];
__device__ __half g_h2h [NTOK * EDIM];
__device__ __half g_th  [NTOK * FFD];
__device__ __half g_W1h [EDIM * FFD];
__device__ __half g_W2h [FFD * EDIM];
__device__ __half g_Woh [EDIM * EDIM];

// ---------------- helpers ----------------
__device__ __forceinline__ float tf32r(float x) {
    uint32_t u;
    asm("cvt.rna.tf32.f32 %0, %1;" : "=r"(u) : "f"(x));
    return __uint_as_float(u);
}
__device__ __forceinline__ void mma_tf32(float* c, const float* a, const float* b) {
    asm volatile(
        "mma.sync.aligned.m16n8k8.row.col.f32.tf32.tf32.f32 "
        "{%0,%1,%2,%3}, {%4,%5,%6,%7}, {%8,%9}, {%0,%1,%2,%3};\n"
        : "+f"(c[0]), "+f"(c[1]), "+f"(c[2]), "+f"(c[3])
        : "r"(__float_as_uint(a[0])), "r"(__float_as_uint(a[1])),
          "r"(__float_as_uint(a[2])), "r"(__float_as_uint(a[3])),
          "r"(__float_as_uint(b[0])), "r"(__float_as_uint(b[1])));
}
__device__ __forceinline__ void mma_f16(float* c, const uint32_t* a, const uint32_t* b) {
    asm volatile(
        "mma.sync.aligned.m16n8k16.row.col.f32.f16.f16.f32 "
        "{%0,%1,%2,%3}, {%4,%5,%6,%7}, {%8,%9}, {%0,%1,%2,%3};\n"
        : "+f"(c[0]), "+f"(c[1]), "+f"(c[2]), "+f"(c[3])
        : "r"(a[0]), "r"(a[1]), "r"(a[2]), "r"(a[3]), "r"(b[0]), "r"(b[1]));
}
__device__ __forceinline__ void cp16(void* s, const void* gp) {
    uint32_t sa = (uint32_t)__cvta_generic_to_shared(s);
    asm volatile("cp.async.cg.shared.global [%0], [%1], 16;\n" :: "r"(sa), "l"(gp));
}
__device__ __forceinline__ void cp_commit() {
    asm volatile("cp.async.commit_group;\n" ::: "memory");
}
__device__ __forceinline__ void cp_wait0() {
    asm volatile("cp.async.wait_group 0;\n" ::: "memory");
}
__device__ __forceinline__ void cp_wait1() {
    asm volatile("cp.async.wait_group 1;\n" ::: "memory");
}
__device__ __forceinline__ void cp_wait2() {
    asm volatile("cp.async.wait_group 2;\n" ::: "memory");
}
__device__ __forceinline__ void ldmx4(uint32_t& r0, uint32_t& r1, uint32_t& r2,
                                      uint32_t& r3, uint32_t addr) {
    asm volatile("ldmatrix.sync.aligned.m8n8.x4.shared.b16 {%0,%1,%2,%3}, [%4];"
                 : "=r"(r0), "=r"(r1), "=r"(r2), "=r"(r3) : "r"(addr));
}
__device__ __forceinline__ void ldmx4t(uint32_t& r0, uint32_t& r1, uint32_t& r2,
                                       uint32_t& r3, uint32_t addr) {
    asm volatile("ldmatrix.sync.aligned.m8n8.x4.trans.shared.b16 {%0,%1,%2,%3}, [%4];"
                 : "=r"(r0), "=r"(r1), "=r"(r2), "=r"(r3) : "r"(addr));
}
__device__ __forceinline__ uint32_t smem_u32(const void* p) {
    return (uint32_t)__cvta_generic_to_shared(p);
}

// ---------------- pack W1/W2/Wo to half ----------------
__global__ void pack_w_kernel(const float* __restrict__ W1,
                              const float* __restrict__ W2,
                              const float* __restrict__ Wo) {
    int i = blockIdx.x * blockDim.x + threadIdx.x;
    if (i < EDIM * FFD) {
        g_W1h[i] = __float2half(W1[i]);
        g_W2h[i] = __float2half(W2[i]);
        if (i < EDIM * EDIM) g_Woh[i] = __float2half(Wo[i]);
    }
}

// ---------------- rmsnorm (f32 out) ----------------
__global__ void rmsnorm_kernel(const float* __restrict__ x,
                               const float* __restrict__ gw,
                               float* __restrict__ y) {
    int warp = (blockIdx.x * blockDim.x + threadIdx.x) >> 5;
    int lane = threadIdx.x & 31;
    if (warp >= NTOK) return;
    float4 v = reinterpret_cast<const float4*>(x + (size_t)warp * EDIM)[lane];
    float ss = v.x * v.x + v.y * v.y + v.z * v.z + v.w * v.w;
    #pragma unroll
    for (int o = 16; o > 0; o >>= 1) ss += __shfl_xor_sync(0xffffffffu, ss, o);
    float s = rsqrtf(ss * (1.0f / 128.0f) + 1e-6f);
    float4 g4 = reinterpret_cast<const float4*>(gw)[lane];
    float4 o4 = make_float4(v.x * s * g4.x, v.y * s * g4.y, v.z * s * g4.z, v.w * s * g4.w);
    reinterpret_cast<float4*>(y + (size_t)warp * EDIM)[lane] = o4;
}

// ---------------------------------------------------------------------------
// Fused QKV GEMM (cp.async double-buffered)
// ---------------------------------------------------------------------------
#define QK_A   4608
#define QK_B   1152
#define QK_BUF (QK_A + 3 * QK_B)
#define QKV_SMEM (2 * QK_BUF * 4)

__global__ __launch_bounds__(256)
void qkv_kernel(const float* __restrict__ h, const float* __restrict__ Wq,
                const float* __restrict__ Wk, const float* __restrict__ Wv) {
    extern __shared__ float smq[];
    const int m0 = blockIdx.x * 128;
    const int j0 = blockIdx.y * 32;
    const int tid = threadIdx.x, lane = tid & 31, warp = tid >> 5;
    const int wm = warp >> 1, wn = warp & 1;
    const int g = lane >> 2, tg = lane & 3;

    const float* Wp[3] = {Wq, Wk, Wv};

    auto cpTile = [&](int buf, int k0) {
        float* As = smq + buf * QK_BUF;
        #pragma unroll
        for (int i = 0; i < 4; i++) {
            int id = tid + i * 256;
            int m = id >> 3, c = (id & 7) << 2;
            cp16(As + m * 36 + c, h + (size_t)(m0 + m) * 128 + k0 + c);
        }
        int k = tid >> 3, c = (tid & 7) << 2;
        #pragma unroll
        for (int w = 0; w < 3; w++)
            cp16(As + QK_A + w * QK_B + k * 36 + c,
                 Wp[w] + (size_t)(k0 + k) * 128 + j0 + c);
    };

    float acc[3][2][2][4];
    #pragma unroll
    for (int w = 0; w < 3; w++)
        #pragma unroll
        for (int i = 0; i < 2; i++)
            #pragma unroll
            for (int j = 0; j < 2; j++)
                #pragma unroll
                for (int r = 0; r < 4; r++) acc[w][i][j][r] = 0.0f;

    cpTile(0, 0);
    cp_commit();

    for (int kt = 0; kt < 4; ++kt) {
        const int buf = kt & 1;
        if (kt + 1 < 4) { cpTile(buf ^ 1, (kt + 1) * 32); cp_commit(); cp_wait1(); }
        else            { cp_wait0(); }
        __syncthreads();
        const float* As = smq + buf * QK_BUF;
        const float* Bs = As + QK_A;
        #pragma unroll
        for (int ks = 0; ks < 4; ++ks) {
            const int kr = ks * 8 + tg;
            float a[2][4];
            #pragma unroll
            for (int mt = 0; mt < 2; ++mt) {
                int m = wm * 32 + mt * 16 + g;
                a[mt][0] = tf32r(As[m * 36 + kr]);
                a[mt][1] = tf32r(As[(m + 8) * 36 + kr]);
                a[mt][2] = tf32r(As[m * 36 + kr + 4]);
                a[mt][3] = tf32r(As[(m + 8) * 36 + kr + 4]);
            }
            #pragma unroll
            for (int w = 0; w < 3; w++) {
                #pragma unroll
                for (int nt = 0; nt < 2; ++nt) {
                    int n = wn * 16 + nt * 8 + g;
                    float bb[2];
                    bb[0] = tf32r(Bs[w * QK_B + kr * 36 + n]);
                    bb[1] = tf32r(Bs[w * QK_B + (kr + 4) * 36 + n]);
                    mma_tf32(acc[w][0][nt], a[0], bb);
                    mma_tf32(acc[w][1][nt], a[1], bb);
                }
            }
        }
        __syncthreads();
    }

    #pragma unroll
    for (int mt = 0; mt < 2; ++mt) {
        #pragma unroll
        for (int nt = 0; nt < 2; ++nt) {
            const int col = j0 + wn * 16 + nt * 8 + tg * 2;
            #pragma unroll
            for (int hh = 0; hh < 2; ++hh) {
                const int row = m0 + wm * 32 + mt * 16 + g + hh * 8;
                float q0 = acc[0][mt][nt][hh * 2], q1 = acc[0][mt][nt][hh * 2 + 1];
                float k0v = acc[1][mt][nt][hh * 2], k1v = acc[1][mt][nt][hh * 2 + 1];
                float v0 = acc[2][mt][nt][hh * 2], v1 = acc[2][mt][nt][hh * 2 + 1];
                float2 s2 = make_float2(1.0f / (1.0f + expf(-q0)),
                                        1.0f / (1.0f + expf(-q1)));
                *reinterpret_cast<float2*>(g_S + (size_t)row * 128 + col) = s2;
                float kw0 = expf(k0v), kw1 = expf(k1v);
                __half2 h0 = __floats2half2_rn(kw0 * v0, kw0);
                __half2 h1 = __floats2half2_rn(kw1 * v1, kw1);
                uint2 u;
                u.x = *reinterpret_cast<uint32_t*>(&h0);
                u.y = *reinterpret_cast<uint32_t*>(&h1);
                *reinterpret_cast<uint2*>(g_Xh + (size_t)row * 256 + 2 * col) = u;
            }
        }
    }
}

// ---------------------------------------------------------------------------
// Big GEMM (fp16 m16n8k16), BK=32.
// A: dis tiles cp.async'd RAW (f32, [k][j]-contiguous) into a 4-deep stage
//    ring; exp+half convert smem->smem (same-thread mapping, no transpose);
//    A fragments via ldmatrix.trans on [k][m] half tile.
// B: same 4-deep ring (one cp group per stage holds both A-f32 and B-half).
// Epilogue: att = sigmoid(q)*w1/w2 -> g_atth (half).
// ---------------------------------------------------------------------------
#define A2_STR 136
#define A2_BUF 4352                  // 32*136 halfs per Ah buffer (x2)
#define AF_OFF 8704                  // half offset of f32 stage ring
#define AF_FLOATS 4096               // 32*128 floats per stage (x4)
#define B2_STR 264
#define B2_BUF 8448                  // 32*264 halfs per stage (x4)
#define B2_OFF (AF_OFF + 4 * AF_FLOATS * 2)   // 41472 halfs
#define BIG_SMEM ((B2_OFF + 4 * B2_BUF) * 2)  // 150528 bytes

__global__ __launch_bounds__(512, 1)
void big_kernel(const float* __restrict__ dis, const float* __restrict__ alphap) {
    extern __shared__ __half smh[];
    __half* Ah = smh;
    float*  Af = reinterpret_cast<float*>(smh + AF_OFF);
    __half* Bh = smh + B2_OFF;
    const uint32_t smb = smem_u32(smh);

    const int tid = threadIdx.x, lane = tid & 31, warp = tid >> 5;
    const int wm = warp >> 2, wn = warp & 3;     // 4m x 4n warps
    const int g = lane >> 2, tg = lane & 3;
    const int b = blockIdx.y, j0 = blockIdx.x * 128;
    const float coef = 12.0f * alphap[0];
    const float* Ag = dis + (size_t)b * NSEQ * NSEQ;
    const __half* Xg = g_Xh + (size_t)b * NSEQ * 256;

    // ldmatrix.trans offsets (halfs within a tile)
    const uint32_t at_off = (uint32_t)((lane & 15) * A2_STR + wm * 32 + ((lane >> 4) << 3));
    const uint32_t bt_off = (uint32_t)((lane & 15) * B2_STR + wn * 64 + ((lane >> 4) << 3));

    float acc[2][8][4];
    #pragma unroll
    for (int i = 0; i < 2; i++)
        #pragma unroll
        for (int j = 0; j < 8; j++)
            #pragma unroll
            for (int r = 0; r < 4; r++) acc[i][j][r] = 0.0f;

    auto cpStage = [&](int s, int k0) {
        #pragma unroll
        for (int it = 0; it < 2; ++it) {
            int id = tid + it * 512;
            int row = id >> 5, c4 = (id & 31) << 2;
            cp16(Af + s * AF_FLOATS + row * 128 + c4,
                 Ag + (size_t)(k0 + row) * NSEQ + j0 + c4);
        }
        #pragma unroll
        for (int it = 0; it < 2; ++it) {
            int id = tid + it * 512;
            int row = id >> 5, cc = (id & 31) << 3;
            cp16(Bh + s * B2_BUF + row * B2_STR + cc,
                 Xg + (size_t)(k0 + row) * 256 + cc);
        }
    };
    // exp+convert stage s (f32) -> Ah buffer d (half). Same-thread mapping as
    // cpStage's A part, so wait_group alone gives visibility (no barrier).
    auto convert = [&](int s, int d) {
        #pragma unroll
        for (int it = 0; it < 2; ++it) {
            int id = tid + it * 512;
            int row = id >> 5, c4 = (id & 31) << 2;
            float4 v = *reinterpret_cast<const float4*>(Af + s * AF_FLOATS + row * 128 + c4);
            __half2 h01 = __floats2half2_rn(__expf(-coef * v.x), __expf(-coef * v.y));
            __half2 h23 = __floats2half2_rn(__expf(-coef * v.z), __expf(-coef * v.w));
            uint2 u;
            u.x = *reinterpret_cast<uint32_t*>(&h01);
            u.y = *reinterpret_cast<uint32_t*>(&h23);
            *reinterpret_cast<uint2*>(Ah + d * A2_BUF + row * A2_STR + c4) = u;
        }
    };

    // prologue: 3 stages in flight, convert stage 0
    cpStage(0, 0);  cp_commit();
    cpStage(1, 32); cp_commit();
    cpStage(2, 64); cp_commit();
    cp_wait2();                 // stage 0 complete
    convert(0, 0);
    __syncthreads();            // Ah buf0 + B stage0 visible to all

    for (int kt = 0; kt < 128; ++kt) {
        const int sb = kt & 3;
        const int ab = kt & 1;
        if (kt + 3 < 128) { cpStage((kt + 3) & 3, (kt + 3) * 32); cp_commit(); cp_wait2(); }
        else if (kt + 1 < 128) { cp_wait0(); }
        if (kt + 1 < 128) convert((kt + 1) & 3, ab ^ 1);

        const uint32_t abase = smb + 2u * (ab * A2_BUF + at_off);
        const uint32_t bbase = smb + 2u * (B2_OFF + sb * B2_BUF + bt_off);
        #pragma unroll
        for (int ks = 0; ks < 2; ++ks) {
            const int kb = ks * 16;
            uint32_t a[2][4];
            #pragma unroll
            for (int mt = 0; mt < 2; ++mt) {
                uint32_t r0, r1, r2, r3;
                ldmx4t(r0, r1, r2, r3, abase + 2u * (kb * A2_STR + mt * 16));
                a[mt][0] = r0; a[mt][1] = r2; a[mt][2] = r1; a[mt][3] = r3;
            }
            #pragma unroll
            for (int np = 0; np < 4; ++np) {
                uint32_t r0, r1, r2, r3;
                ldmx4t(r0, r1, r2, r3, bbase + 2u * (kb * B2_STR + np * 16));
                uint32_t b0[2] = {r0, r1}, b1[2] = {r2, r3};
                mma_f16(acc[0][np * 2],     a[0], b0);
                mma_f16(acc[1][np * 2],     a[1], b0);
                mma_f16(acc[0][np * 2 + 1], a[0], b1);
                mma_f16(acc[1][np * 2 + 1], a[1], b1);
            }
        }
        __syncthreads();
    }

    // epilogue: att = S * w1/w2 -> half
    const size_t rowbase = (size_t)b * NSEQ + j0;
    #pragma unroll
    for (int mt = 0; mt < 2; ++mt) {
        const int r0 = wm * 32 + mt * 16 + g;
        #pragma unroll
        for (int nt = 0; nt < 8; ++nt) {
            const int e = wn * 32 + nt * 4 + tg;
            const size_t i0 = (rowbase + r0) * 128 + e;
            const size_t i1 = (rowbase + r0 + 8) * 128 + e;
            float a0 = g_S[i0] * __fdividef(acc[mt][nt][0], acc[mt][nt][1]);
            float a1 = g_S[i1] * __fdividef(acc[mt][nt][2], acc[mt][nt][3]);
            g_atth[i0] = __float2half(a0);
            g_atth[i1] = __float2half(a1);
        }
    }
}

// ---------------------------------------------------------------------------
// Wo (fp16 resident) + residual + fused post-rmsnorm (unchanged from R11)
// ---------------------------------------------------------------------------
#define WO_STR 136
#define WO_BOFF 17408
#define WO_SMEM (2 * WO_BOFF * 2)

__global__ __launch_bounds__(256)
void wo_norm_kernel(const float* __restrict__ x, const float* __restrict__ gpost,
                    float* __restrict__ out1) {
    extern __shared__ __half smw[];
    __shared__ float rowss[128];
    __half* Ah = smw;
    __half* Bh = smw + WO_BOFF;
    const uint32_t smb = smem_u32(smw);

    const int m0 = blockIdx.x * 128;
    const int tid = threadIdx.x, lane = tid & 31, warp = tid >> 5;
    const int wm = warp >> 1, wn = warp & 1;
    const int g = lane >> 2, tg = lane & 3;
    const int lr = lane & 7, sel = lane >> 3;

    #pragma unroll
    for (int i = 0; i < 8; i++) {
        int id = tid + i * 256;
        int m = id >> 4, c = (id & 15) << 3;
        cp16(Ah + m * WO_STR + c, g_atth + (size_t)(m0 + m) * 128 + c);
        cp16(Bh + m * WO_STR + c, g_Woh + (size_t)m * 128 + c);
    }
    cp_commit();
    if (tid < 128) rowss[tid] = 0.0f;
    cp_wait0();
    __syncthreads();

    uint32_t aoff[2];
    #pragma unroll
    for (int mt = 0; mt < 2; ++mt)
        aoff[mt] = (uint32_t)((wm * 32 + mt * 16 + (sel & 1) * 8 + lr) * WO_STR +
                              (sel >> 1) * 8);
    const uint32_t lm = (uint32_t)((lane & 15) * WO_STR + wn * 64 + ((lane >> 4) << 3));

    float acc[2][8][4];
    #pragma unroll
    for (int i = 0; i < 2; i++)
        #pragma unroll
        for (int j = 0; j < 8; j++)
            #pragma unroll
            for (int r = 0; r < 4; r++) acc[i][j][r] = 0.0f;

    #pragma unroll
    for (int kb = 0; kb < 128; kb += 16) {
        uint32_t a[2][4];
        #pragma unroll
        for (int mt = 0; mt < 2; ++mt)
            ldmx4(a[mt][0], a[mt][1], a[mt][2], a[mt][3],
                  smb + 2u * (aoff[mt] + kb));
        #pragma unroll
        for (int np = 0; np < 4; ++np) {
            uint32_t r0, r1, r2, r3;
            ldmx4t(r0, r1, r2, r3, smb + 2u * (WO_BOFF + lm + kb * WO_STR + np * 16));
            uint32_t b0[2] = {r0, r1}, b1r[2] = {r2, r3};
            mma_f16(acc[0][np * 2],     a[0], b0);
            mma_f16(acc[1][np * 2],     a[1], b0);
            mma_f16(acc[0][np * 2 + 1], a[0], b1r);
            mma_f16(acc[1][np * 2 + 1], a[1], b1r);
        }
    }

    #pragma unroll
    for (int mt = 0; mt < 2; ++mt) {
        #pragma unroll
        for (int h = 0; h < 2; ++h) {
            const int rl = wm * 32 + mt * 16 + g + h * 8;
            const size_t rowg = (size_t)(m0 + rl);
            float ss = 0.0f;
            #pragma unroll
            for (int nt = 0; nt < 8; ++nt) {
                const int c = wn * 64 + nt * 8 + tg * 2;
                float2 xv = *reinterpret_cast<const float2*>(x + rowg * 128 + c);
                float v0 = acc[mt][nt][h * 2 + 0] + xv.x;
                float v1 = acc[mt][nt][h * 2 + 1] + xv.y;
                acc[mt][nt][h * 2 + 0] = v0;
                acc[mt][nt][h * 2 + 1] = v1;
                *reinterpret_cast<float2*>(out1 + rowg * 128 + c) = make_float2(v0, v1);
                ss += v0 * v0 + v1 * v1;
            }
            ss += __shfl_xor_sync(0xffffffffu, ss, 1);
            ss += __shfl_xor_sync(0xffffffffu, ss, 2);
            if (tg == 0) atomicAdd(&rowss[rl], ss);
        }
    }
    __syncthreads();

    #pragma unroll
    for (int mt = 0; mt < 2; ++mt) {
        #pragma unroll
        for (int h = 0; h < 2; ++h) {
            const int rl = wm * 32 + mt * 16 + g + h * 8;
            const size_t rowg = (size_t)(m0 + rl);
            const float sc = rsqrtf(rowss[rl] * (1.0f / 128.0f) + 1e-6f);
            #pragma unroll
            for (int nt = 0; nt < 8; ++nt) {
                const int c = wn * 64 + nt * 8 + tg * 2;
                float2 gp = *reinterpret_cast<const float2*>(gpost + c);
                __half2 hv = __floats2half2_rn(acc[mt][nt][h * 2 + 0] * sc * gp.x,
                                               acc[mt][nt][h * 2 + 1] * sc * gp.y);
                *reinterpret_cast<uint32_t*>(g_h2h + rowg * 128 + c) =
                    *reinterpret_cast<uint32_t*>(&hv);
            }
        }
    }
}

// ---------------------------------------------------------------------------
// FF1 (fp16 resident, unchanged)
// ---------------------------------------------------------------------------
#define F1_ASTR 136
#define F1_BOFF 17408
#define F1_BSTR 72
#define F1_SMEM ((F1_BOFF + 128 * F1_BSTR) * 2)

__global__ __launch_bounds__(256)
void ff1_kernel(const float* __restrict__ b1) {
    extern __shared__ __half smf[];
    __half* Ah = smf;
    __half* Bh = smf + F1_BOFF;
    const uint32_t smb = smem_u32(smf);

    const int m0 = blockIdx.x * 128;
    const int n0 = blockIdx.y * 64;
    const int tid = threadIdx.x, lane = tid & 31, warp = tid >> 5;
    const int wm = warp >> 1, wn = warp & 1;
    const int g = lane >> 2, tg = lane & 3;
    const int lr = lane & 7, sel = lane >> 3;

    #pragma unroll
    for (int i = 0; i < 8; i++) {
        int id = tid + i * 256;
        int m = id >> 4, c = (id & 15) << 3;
        cp16(Ah + m * F1_ASTR + c, g_h2h + (size_t)(m0 + m) * 128 + c);
    }
    #pragma unroll
    for (int i = 0; i < 4; i++) {
        int id = tid + i * 256;
        int k = id >> 3, c = (id & 7) << 3;
        cp16(Bh + k * F1_BSTR + c, g_W1h + (size_t)k * FFD + n0 + c);
    }
    cp_commit();
    cp_wait0();
    __syncthreads();

    uint32_t aoff[2];
    #pragma unroll
    for (int mt = 0; mt < 2; ++mt)
        aoff[mt] = (uint32_t)((wm * 32 + mt * 16 + (sel & 1) * 8 + lr) * F1_ASTR +
                              (sel >> 1) * 8);
    const uint32_t lm = (uint32_t)((lane & 15) * F1_BSTR + wn * 32 + ((lane >> 4) << 3));

    float acc[2][4][4];
    #pragma unroll
    for (int i = 0; i < 2; i++)
        #pragma unroll
        for (int j = 0; j < 4; j++)
            #pragma unroll
            for (int r = 0; r < 4; r++) acc[i][j][r] = 0.0f;

    #pragma unroll
    for (int kb = 0; kb < 128; kb += 16) {
        uint32_t a[2][4];
        #pragma unroll
        for (int mt = 0; mt < 2; ++mt)
            ldmx4(a[mt][0], a[mt][1], a[mt][2], a[mt][3],
                  smb + 2u * (aoff[mt] + kb));
        #pragma unroll
        for (int np = 0; np < 2; ++np) {
            uint32_t r0, r1, r2, r3;
            ldmx4t(r0, r1, r2, r3,
                   smb + 2u * (F1_BOFF + lm + kb * F1_BSTR + np * 16));
            uint32_t b0[2] = {r0, r1}, b1r[2] = {r2, r3};
            mma_f16(acc[0][np * 2],     a[0], b0);
            mma_f16(acc[1][np * 2],     a[1], b0);
            mma_f16(acc[0][np * 2 + 1], a[0], b1r);
            mma_f16(acc[1][np * 2 + 1], a[1], b1r);
        }
    }

    #pragma unroll
    for (int mt = 0; mt < 2; ++mt) {
        #pragma unroll
        for (int nt = 0; nt < 4; ++nt) {
            const int col = n0 + wn * 32 + nt * 8 + tg * 2;
            const float bb0 = b1[col], bb1 = b1[col + 1];
            #pragma unroll
            for (int h = 0; h < 2; ++h) {
                const int row = m0 + wm * 32 + mt * 16 + g + h * 8;
                float v0 = fmaxf(acc[mt][nt][h * 2 + 0] + bb0, 0.0f);
                float v1 = fmaxf(acc[mt][nt][h * 2 + 1] + bb1, 0.0f);
                __half2 hv = __floats2half2_rn(v0, v1);
                *reinterpret_cast<uint32_t*>(g_th + (size_t)row * FFD + col) =
                    *reinterpret_cast<uint32_t*>(&hv);
            }
        }
    }
}

// ---------------------------------------------------------------------------
// FF2 (fp16, BK=64 double-buffered, unchanged)
// ---------------------------------------------------------------------------
#define F2_ASTR 72
#define F2_ABUF 9216
#define F2_BSTR 136
#define F2_BBUF 8704
#define F2_STAGE (F2_ABUF + F2_BBUF)
#define F2_SMEM (2 * F2_STAGE * 2)

__global__ __launch_bounds__(256)
void ff2_kernel(const float* __restrict__ b2, const float* __restrict__ res,
                float* __restrict__ out) {
    extern __shared__ __half smf[];
    const uint32_t smb = smem_u32(smf);

    const int m0 = blockIdx.x * 128;
    const int tid = threadIdx.x, lane = tid & 31, warp = tid >> 5;
    const int wm = warp >> 1, wn = warp & 1;
    const int g = lane >> 2, tg = lane & 3;
    const int lr = lane & 7, sel = lane >> 3;

    auto cpTile = [&](int stage, int k0) {
        __half* As = smf + stage * F2_STAGE;
        __half* Bs = As + F2_ABUF;
        #pragma unroll
        for (int i = 0; i < 4; i++) {
            int id = tid + i * 256;
            int m = id >> 3, c = (id & 7) << 3;
            cp16(As + m * F2_ASTR + c, g_th + (size_t)(m0 + m) * FFD + k0 + c);
        }
        #pragma unroll
        for (int i = 0; i < 4; i++) {
            int id = tid + i * 256;
            int k = id >> 4, c = (id & 15) << 3;
            cp16(Bs + k * F2_BSTR + c, g_W2h + (size_t)(k0 + k) * EDIM + c);
        }
    };

    uint32_t aoff[2];
    #pragma unroll
    for (int mt = 0; mt < 2; ++mt)
        aoff[mt] = (uint32_t)((wm * 32 + mt * 16 + (sel & 1) * 8 + lr) * F2_ASTR +
                              (sel >> 1) * 8);
    const uint32_t lm = (uint32_t)((lane & 15) * F2_BSTR + wn * 64 + ((lane >> 4) << 3));

    float acc[2][8][4];
    #pragma unroll
    for (int i = 0; i < 2; i++)
        #pragma unroll
        for (int j = 0; j < 8; j++)
            #pragma unroll
            for (int r = 0; r < 4; r++) acc[i][j][r] = 0.0f;

    cpTile(0, 0);
    cp_commit();

    for (int kt = 0; kt < 8; ++kt) {
        const int stage = kt & 1;
        if (kt + 1 < 8) { cpTile(stage ^ 1, (kt + 1) * 64); cp_commit(); cp_wait1(); }
        else            { cp_wait0(); }
        __syncthreads();
        const uint32_t abase = smb + 2u * (stage * F2_STAGE);
        const uint32_t bbase = smb + 2u * (stage * F2_STAGE + F2_ABUF + lm);
        #pragma unroll
        for (int ks = 0; ks < 4; ++ks) {
            const int kb = ks * 16;
            uint32_t a[2][4];
            #pragma unroll
            for (int mt = 0; mt < 2; ++mt)
                ldmx4(a[mt][0], a[mt][1], a[mt][2], a[mt][3],
                      abase + 2u * (aoff[mt] + kb));
            #pragma unroll
            for (int np = 0; np < 4; ++np) {
                uint32_t r0, r1, r2, r3;
                ldmx4t(r0, r1, r2, r3, bbase + 2u * (kb * F2_BSTR + np * 16));
                uint32_t b0[2] = {r0, r1}, b1r[2] = {r2, r3};
                mma_f16(acc[0][np * 2],     a[0], b0);
                mma_f16(acc[1][np * 2],     a[1], b0);
                mma_f16(acc[0][np * 2 + 1], a[0], b1r);
                mma_f16(acc[1][np * 2 + 1], a[1], b1r);
            }
        }
        __syncthreads();
    }

    #pragma unroll
    for (int mt = 0; mt < 2; ++mt) {
        #pragma unroll
        for (int nt = 0; nt < 8; ++nt) {
            const int col = wn * 64 + nt * 8 + tg * 2;
            const float bb0 = b2[col], bb1 = b2[col + 1];
            #pragma unroll
            for (int h = 0; h < 2; ++h) {
                const int row = m0 + wm * 32 + mt * 16 + g + h * 8;
                float v0 = acc[mt][nt][h * 2 + 0] + bb0 + res[(size_t)row * 128 + col];
                float v1 = acc[mt][nt][h * 2 + 1] + bb1 + res[(size_t)row * 128 + col + 1];
                out[(size_t)row * 128 + col]     = v0;
                out[(size_t)row * 128 + col + 1] = v1;
            }
        }
    }
}

// ---------------- launch ----------------
extern "C" void kernel_launch(void* const* d_in, const int* in_sizes, int n_in,
                              void* d_out, int out_size) {
    const float* x     = (const float*)d_in[0];
    const float* dis   = (const float*)d_in[1];
    const float* g_in  = (const float*)d_in[2];
    const float* g_po  = (const float*)d_in[3];
    const float* Wq    = (const float*)d_in[4];
    const float* Wk    = (const float*)d_in[5];
    const float* Wv    = (const float*)d_in[6];
    const float* alpha = (const float*)d_in[7];
    const float* Wo    = (const float*)d_in[8];
    const float* W1    = (const float*)d_in[9];
    const float* b1    = (const float*)d_in[10];
    const float* W2    = (const float*)d_in[11];
    const float* b2    = (const float*)d_in[12];
    float* out = (float*)d_out;

    float *p_h, *p_out1;
    cudaGetSymbolAddress((void**)&p_h,    g_h);
    cudaGetSymbolAddress((void**)&p_out1, g_out1);

    cudaFuncSetAttribute(big_kernel,
                         cudaFuncAttributeMaxDynamicSharedMemorySize, BIG_SMEM);
    cudaFuncSetAttribute(qkv_kernel,
                         cudaFuncAttributeMaxDynamicSharedMemorySize, QKV_SMEM);
    cudaFuncSetAttribute(wo_norm_kernel,
                         cudaFuncAttributeMaxDynamicSharedMemorySize, WO_SMEM);
    cudaFuncSetAttribute(ff1_kernel,
                         cudaFuncAttributeMaxDynamicSharedMemorySize, F1_SMEM);
    cudaFuncSetAttribute(ff2_kernel,
                         cudaFuncAttributeMaxDynamicSharedMemorySize, F2_SMEM);

    pack_w_kernel<<<(EDIM * FFD + 255) / 256, 256>>>(W1, W2, Wo);
    rmsnorm_kernel<<<NTOK / 8, 256>>>(x, g_in, p_h);
    qkv_kernel<<<dim3(NTOK / 128, 4), 256, QKV_SMEM>>>(p_h, Wq, Wk, Wv);
    big_kernel<<<dim3(NSEQ / 128, NB), 512, BIG_SMEM>>>(dis, alpha);
    wo_norm_kernel<<<NTOK / 128, 256, WO_SMEM>>>(x, g_po, p_out1);
    ff1_kernel<<<dim3(NTOK / 128, 8), 256, F1_SMEM>>>(b1);
    ff2_kernel<<<NTOK / 128, 256, F2_SMEM>>>(b2, p_out1, out);
}

// round 13
// speedup vs baseline: 1.1583x; 1.1583x over previous
#include <cuda_runtime.h>
#include <cuda_fp16.h>
#include <cstdint>
#include <cstddef>

#define NB     4
#define NSEQ   4096
#define EDIM   128
#define FFD    512
#define NTOK   (NB * NSEQ)

// ---------------- scratch ----------------
__device__ float  g_h   [NTOK * EDIM];
__device__ float  g_S   [NTOK * EDIM];
__device__ __half g_Xh  [NTOK * 256];
__device__ __half g_atth[NTOK * EDIM];
__device__ float  g_out1[NTOK * EDIM];
__device__ __half g_h2h [NTOK * EDIM];
__device__ __half g_th  [NTOK * FFD];
__device__ __half g_W1h [EDIM * FFD];
__device__ __half g_W2h [FFD * EDIM];
__device__ __half g_Woh [EDIM * EDIM];

// ---------------- helpers ----------------
__device__ __forceinline__ float tf32r(float x) {
    uint32_t u;
    asm("cvt.rna.tf32.f32 %0, %1;" : "=r"(u) : "f"(x));
    return __uint_as_float(u);
}
__device__ __forceinline__ void mma_tf32(float* c, const float* a, const float* b) {
    asm volatile(
        "mma.sync.aligned.m16n8k8.row.col.f32.tf32.tf32.f32 "
        "{%0,%1,%2,%3}, {%4,%5,%6,%7}, {%8,%9}, {%0,%1,%2,%3};\n"
        : "+f"(c[0]), "+f"(c[1]), "+f"(c[2]), "+f"(c[3])
        : "r"(__float_as_uint(a[0])), "r"(__float_as_uint(a[1])),
          "r"(__float_as_uint(a[2])), "r"(__float_as_uint(a[3])),
          "r"(__float_as_uint(b[0])), "r"(__float_as_uint(b[1])));
}
__device__ __forceinline__ void mma_f16(float* c, const uint32_t* a, const uint32_t* b) {
    asm volatile(
        "mma.sync.aligned.m16n8k16.row.col.f32.f16.f16.f32 "
        "{%0,%1,%2,%3}, {%4,%5,%6,%7}, {%8,%9}, {%0,%1,%2,%3};\n"
        : "+f"(c[0]), "+f"(c[1]), "+f"(c[2]), "+f"(c[3])
        : "r"(a[0]), "r"(a[1]), "r"(a[2]), "r"(a[3]), "r"(b[0]), "r"(b[1]));
}
__device__ __forceinline__ void cp16(void* s, const void* gp) {
    uint32_t sa = (uint32_t)__cvta_generic_to_shared(s);
    asm volatile("cp.async.cg.shared.global [%0], [%1], 16;\n" :: "r"(sa), "l"(gp));
}
__device__ __forceinline__ void cp_commit() {
    asm volatile("cp.async.commit_group;\n" ::: "memory");
}
__device__ __forceinline__ void cp_wait0() {
    asm volatile("cp.async.wait_group 0;\n" ::: "memory");
}
__device__ __forceinline__ void cp_wait1() {
    asm volatile("cp.async.wait_group 1;\n" ::: "memory");
}
__device__ __forceinline__ void ldmx4(uint32_t& r0, uint32_t& r1, uint32_t& r2,
                                      uint32_t& r3, uint32_t addr) {
    asm volatile("ldmatrix.sync.aligned.m8n8.x4.shared.b16 {%0,%1,%2,%3}, [%4];"
                 : "=r"(r0), "=r"(r1), "=r"(r2), "=r"(r3) : "r"(addr));
}
__device__ __forceinline__ void ldmx4t(uint32_t& r0, uint32_t& r1, uint32_t& r2,
                                       uint32_t& r3, uint32_t addr) {
    asm volatile("ldmatrix.sync.aligned.m8n8.x4.trans.shared.b16 {%0,%1,%2,%3}, [%4];"
                 : "=r"(r0), "=r"(r1), "=r"(r2), "=r"(r3) : "r"(addr));
}
__device__ __forceinline__ uint32_t smem_u32(const void* p) {
    return (uint32_t)__cvta_generic_to_shared(p);
}

// ---------------------------------------------------------------------------
// Prep: blocks [0, 2048): rmsnorm(x) -> g_h ; blocks [2048, 2304): pack W1/W2/Wo
// ---------------------------------------------------------------------------
__global__ void prep_kernel(const float* __restrict__ x,
                            const float* __restrict__ gw,
                            float* __restrict__ y,
                            const float* __restrict__ W1,
                            const float* __restrict__ W2,
                            const float* __restrict__ Wo) {
    if (blockIdx.x < 2048) {
        int warp = (blockIdx.x * blockDim.x + threadIdx.x) >> 5;
        int lane = threadIdx.x & 31;
        float4 v = reinterpret_cast<const float4*>(x + (size_t)warp * EDIM)[lane];
        float ss = v.x * v.x + v.y * v.y + v.z * v.z + v.w * v.w;
        #pragma unroll
        for (int o = 16; o > 0; o >>= 1) ss += __shfl_xor_sync(0xffffffffu, ss, o);
        float s = rsqrtf(ss * (1.0f / 128.0f) + 1e-6f);
        float4 g4 = reinterpret_cast<const float4*>(gw)[lane];
        float4 o4 = make_float4(v.x * s * g4.x, v.y * s * g4.y,
                                v.z * s * g4.z, v.w * s * g4.w);
        reinterpret_cast<float4*>(y + (size_t)warp * EDIM)[lane] = o4;
    } else {
        int i = (blockIdx.x - 2048) * blockDim.x + threadIdx.x;   // < 65536
        g_W1h[i] = __float2half(W1[i]);
        g_W2h[i] = __float2half(W2[i]);
        if (i < EDIM * EDIM) g_Woh[i] = __float2half(Wo[i]);
    }
}

// ---------------------------------------------------------------------------
// Fused QKV GEMM (cp.async double-buffered)
// ---------------------------------------------------------------------------
#define QK_A   4608
#define QK_B   1152
#define QK_BUF (QK_A + 3 * QK_B)
#define QKV_SMEM (2 * QK_BUF * 4)

__global__ __launch_bounds__(256)
void qkv_kernel(const float* __restrict__ h, const float* __restrict__ Wq,
                const float* __restrict__ Wk, const float* __restrict__ Wv) {
    extern __shared__ float smq[];
    const int m0 = blockIdx.x * 128;
    const int j0 = blockIdx.y * 32;
    const int tid = threadIdx.x, lane = tid & 31, warp = tid >> 5;
    const int wm = warp >> 1, wn = warp & 1;
    const int g = lane >> 2, tg = lane & 3;

    const float* Wp[3] = {Wq, Wk, Wv};

    auto cpTile = [&](int buf, int k0) {
        float* As = smq + buf * QK_BUF;
        #pragma unroll
        for (int i = 0; i < 4; i++) {
            int id = tid + i * 256;
            int m = id >> 3, c = (id & 7) << 2;
            cp16(As + m * 36 + c, h + (size_t)(m0 + m) * 128 + k0 + c);
        }
        int k = tid >> 3, c = (tid & 7) << 2;
        #pragma unroll
        for (int w = 0; w < 3; w++)
            cp16(As + QK_A + w * QK_B + k * 36 + c,
                 Wp[w] + (size_t)(k0 + k) * 128 + j0 + c);
    };

    float acc[3][2][2][4];
    #pragma unroll
    for (int w = 0; w < 3; w++)
        #pragma unroll
        for (int i = 0; i < 2; i++)
            #pragma unroll
            for (int j = 0; j < 2; j++)
                #pragma unroll
                for (int r = 0; r < 4; r++) acc[w][i][j][r] = 0.0f;

    cpTile(0, 0);
    cp_commit();

    for (int kt = 0; kt < 4; ++kt) {
        const int buf = kt & 1;
        if (kt + 1 < 4) { cpTile(buf ^ 1, (kt + 1) * 32); cp_commit(); cp_wait1(); }
        else            { cp_wait0(); }
        __syncthreads();
        const float* As = smq + buf * QK_BUF;
        const float* Bs = As + QK_A;
        #pragma unroll
        for (int ks = 0; ks < 4; ++ks) {
            const int kr = ks * 8 + tg;
            float a[2][4];
            #pragma unroll
            for (int mt = 0; mt < 2; ++mt) {
                int m = wm * 32 + mt * 16 + g;
                a[mt][0] = tf32r(As[m * 36 + kr]);
                a[mt][1] = tf32r(As[(m + 8) * 36 + kr]);
                a[mt][2] = tf32r(As[m * 36 + kr + 4]);
                a[mt][3] = tf32r(As[(m + 8) * 36 + kr + 4]);
            }
            #pragma unroll
            for (int w = 0; w < 3; w++) {
                #pragma unroll
                for (int nt = 0; nt < 2; ++nt) {
                    int n = wn * 16 + nt * 8 + g;
                    float bb[2];
                    bb[0] = tf32r(Bs[w * QK_B + kr * 36 + n]);
                    bb[1] = tf32r(Bs[w * QK_B + (kr + 4) * 36 + n]);
                    mma_tf32(acc[w][0][nt], a[0], bb);
                    mma_tf32(acc[w][1][nt], a[1], bb);
                }
            }
        }
        __syncthreads();
    }

    #pragma unroll
    for (int mt = 0; mt < 2; ++mt) {
        #pragma unroll
        for (int nt = 0; nt < 2; ++nt) {
            const int col = j0 + wn * 16 + nt * 8 + tg * 2;
            #pragma unroll
            for (int hh = 0; hh < 2; ++hh) {
                const int row = m0 + wm * 32 + mt * 16 + g + hh * 8;
                float q0 = acc[0][mt][nt][hh * 2], q1 = acc[0][mt][nt][hh * 2 + 1];
                float k0v = acc[1][mt][nt][hh * 2], k1v = acc[1][mt][nt][hh * 2 + 1];
                float v0 = acc[2][mt][nt][hh * 2], v1 = acc[2][mt][nt][hh * 2 + 1];
                float2 s2 = make_float2(1.0f / (1.0f + expf(-q0)),
                                        1.0f / (1.0f + expf(-q1)));
                *reinterpret_cast<float2*>(g_S + (size_t)row * 128 + col) = s2;
                float kw0 = expf(k0v), kw1 = expf(k1v);
                __half2 h0 = __floats2half2_rn(kw0 * v0, kw0);
                __half2 h1 = __floats2half2_rn(kw1 * v1, kw1);
                uint2 u;
                u.x = *reinterpret_cast<uint32_t*>(&h0);
                u.y = *reinterpret_cast<uint32_t*>(&h1);
                *reinterpret_cast<uint2*>(g_Xh + (size_t)row * 256 + 2 * col) = u;
            }
        }
    }
}

// ---------------------------------------------------------------------------
// Big GEMM (fp16 m16n8k16) — R10 structure verbatim (127 µs measured):
// BK=32, A: strided LDG f32 -> exp -> STS half [m][40]; fragments ldmatrix.x4.
// B: 3-stage cp.async, [k][264] rows, fragments ldmatrix.x4.trans.
// Epilogue: att = sigmoid(q)*w1/w2 -> g_atth (half).
// ---------------------------------------------------------------------------
#define AH_STR 40
#define AH_BUF 5120
#define BH_STR 264
#define BH_BUF 8448
#define BH_OFF 10240
#define BIG_SMEM 71168

__global__ __launch_bounds__(512, 1)
void big_kernel(const float* __restrict__ dis, const float* __restrict__ alphap) {
    extern __shared__ __half smh[];
    __half* Ah = smh;
    __half* Bh = smh + BH_OFF;
    const uint32_t smb = smem_u32(smh);

    const int tid = threadIdx.x, lane = tid & 31, warp = tid >> 5;
    const int wm = warp >> 2, wn = warp & 3;
    const int g = lane >> 2, tg = lane & 3;
    const int b = blockIdx.y, j0 = blockIdx.x * 128;
    const float coef = 12.0f * alphap[0];
    const float* Ag = dis + (size_t)b * NSEQ * NSEQ;
    const __half* Xg = g_Xh + (size_t)b * NSEQ * 256;

    const int am = tid & 127, ar4 = (tid >> 7) << 2;

    const int lr = lane & 7, sel = lane >> 3;
    uint32_t aoff[2];
    #pragma unroll
    for (int mt = 0; mt < 2; ++mt)
        aoff[mt] = (uint32_t)((wm * 32 + mt * 16 + (sel & 1) * 8 + lr) * AH_STR +
                              (sel >> 1) * 8);
    const uint32_t lm_half = (uint32_t)((lane & 15) * BH_STR + wn * 64 + ((lane >> 4) << 3));

    float ra[2][4];
    float acc[2][8][4];
    #pragma unroll
    for (int i = 0; i < 2; i++)
        #pragma unroll
        for (int j = 0; j < 8; j++)
            #pragma unroll
            for (int r = 0; r < 4; r++) acc[i][j][r] = 0.0f;

    auto ldA = [&](int k0) {
        #pragma unroll
        for (int it = 0; it < 2; ++it) {
            const float* p = Ag + (size_t)(k0 + it * 16 + ar4) * NSEQ + j0 + am;
            ra[it][0] = p[0]; ra[it][1] = p[NSEQ];
            ra[it][2] = p[2 * NSEQ]; ra[it][3] = p[3 * NSEQ];
        }
    };
    auto stA = [&](int buf) {
        __half* base = Ah + buf * AH_BUF + am * AH_STR;
        #pragma unroll
        for (int it = 0; it < 2; ++it) {
            __half2 h01 = __floats2half2_rn(__expf(-coef * ra[it][0]),
                                            __expf(-coef * ra[it][1]));
            __half2 h23 = __floats2half2_rn(__expf(-coef * ra[it][2]),
                                            __expf(-coef * ra[it][3]));
            uint2 u;
            u.x = *reinterpret_cast<uint32_t*>(&h01);
            u.y = *reinterpret_cast<uint32_t*>(&h23);
            *reinterpret_cast<uint2*>(base + it * 16 + ar4) = u;
        }
    };
    auto cpB = [&](int stage, int k0) {
        #pragma unroll
        for (int it = 0; it < 2; ++it) {
            int ch = tid + it * 512;
            int row = ch >> 5, cc = (ch & 31) << 3;
            cp16(Bh + stage * BH_BUF + row * BH_STR + cc,
                 Xg + (size_t)(k0 + row) * 256 + cc);
        }
    };

    cpB(0, 0);  cp_commit();
    cpB(1, 32); cp_commit();
    ldA(0);
    stA(0);
    cp_wait1();
    __syncthreads();

    for (int kt = 0; kt < 128; ++kt) {
        const int sbuf = kt % 3;
        const int abuf = kt & 1;
        if (kt + 2 < 128) { cpB((kt + 2) % 3, (kt + 2) * 32); cp_commit(); }
        if (kt + 1 < 128) ldA((kt + 1) * 32);

        const uint32_t abase = smb + 2u * (abuf * AH_BUF);
        const uint32_t bbase = smb + 2u * (BH_OFF + sbuf * BH_BUF + lm_half);
        #pragma unroll
        for (int ks = 0; ks < 2; ++ks) {
            const int kb = ks * 16;
            uint32_t a[2][4];
            #pragma unroll
            for (int mt = 0; mt < 2; ++mt)
                ldmx4(a[mt][0], a[mt][1], a[mt][2], a[mt][3],
                      abase + 2u * (aoff[mt] + kb));
            #pragma unroll
            for (int np = 0; np < 4; ++np) {
                uint32_t r0, r1, r2, r3;
                ldmx4t(r0, r1, r2, r3, bbase + 2u * (kb * BH_STR + np * 16));
                uint32_t b0[2] = {r0, r1}, b1[2] = {r2, r3};
                mma_f16(acc[0][np * 2],     a[0], b0);
                mma_f16(acc[1][np * 2],     a[1], b0);
                mma_f16(acc[0][np * 2 + 1], a[0], b1);
                mma_f16(acc[1][np * 2 + 1], a[1], b1);
            }
        }
        if (kt + 1 < 128) stA(abuf ^ 1);
        cp_wait1();
        __syncthreads();
    }

    // epilogue: att = S * w1/w2 -> half
    const size_t rowbase = (size_t)b * NSEQ + j0;
    #pragma unroll
    for (int mt = 0; mt < 2; ++mt) {
        const int r0 = wm * 32 + mt * 16 + g;
        #pragma unroll
        for (int nt = 0; nt < 8; ++nt) {
            const int e = wn * 32 + nt * 4 + tg;
            const size_t i0 = (rowbase + r0) * 128 + e;
            const size_t i1 = (rowbase + r0 + 8) * 128 + e;
            float a0 = g_S[i0] * __fdividef(acc[mt][nt][0], acc[mt][nt][1]);
            float a1 = g_S[i1] * __fdividef(acc[mt][nt][2], acc[mt][nt][3]);
            g_atth[i0] = __float2half(a0);
            g_atth[i1] = __float2half(a1);
        }
    }
}

// ---------------------------------------------------------------------------
// Wo (fp16 resident) + residual + fused post-rmsnorm (R11, measured good)
// ---------------------------------------------------------------------------
#define WO_STR 136
#define WO_BOFF 17408
#define WO_SMEM (2 * WO_BOFF * 2)

__global__ __launch_bounds__(256)
void wo_norm_kernel(const float* __restrict__ x, const float* __restrict__ gpost,
                    float* __restrict__ out1) {
    extern __shared__ __half smw[];
    __shared__ float rowss[128];
    __half* Ah = smw;
    __half* Bh = smw + WO_BOFF;
    const uint32_t smb = smem_u32(smw);

    const int m0 = blockIdx.x * 128;
    const int tid = threadIdx.x, lane = tid & 31, warp = tid >> 5;
    const int wm = warp >> 1, wn = warp & 1;
    const int g = lane >> 2, tg = lane & 3;
    const int lr = lane & 7, sel = lane >> 3;

    #pragma unroll
    for (int i = 0; i < 8; i++) {
        int id = tid + i * 256;
        int m = id >> 4, c = (id & 15) << 3;
        cp16(Ah + m * WO_STR + c, g_atth + (size_t)(m0 + m) * 128 + c);
        cp16(Bh + m * WO_STR + c, g_Woh + (size_t)m * 128 + c);
    }
    cp_commit();
    if (tid < 128) rowss[tid] = 0.0f;
    cp_wait0();
    __syncthreads();

    uint32_t aoff[2];
    #pragma unroll
    for (int mt = 0; mt < 2; ++mt)
        aoff[mt] = (uint32_t)((wm * 32 + mt * 16 + (sel & 1) * 8 + lr) * WO_STR +
                              (sel >> 1) * 8);
    const uint32_t lm = (uint32_t)((lane & 15) * WO_STR + wn * 64 + ((lane >> 4) << 3));

    float acc[2][8][4];
    #pragma unroll
    for (int i = 0; i < 2; i++)
        #pragma unroll
        for (int j = 0; j < 8; j++)
            #pragma unroll
            for (int r = 0; r < 4; r++) acc[i][j][r] = 0.0f;

    #pragma unroll
    for (int kb = 0; kb < 128; kb += 16) {
        uint32_t a[2][4];
        #pragma unroll
        for (int mt = 0; mt < 2; ++mt)
            ldmx4(a[mt][0], a[mt][1], a[mt][2], a[mt][3],
                  smb + 2u * (aoff[mt] + kb));
        #pragma unroll
        for (int np = 0; np < 4; ++np) {
            uint32_t r0, r1, r2, r3;
            ldmx4t(r0, r1, r2, r3, smb + 2u * (WO_BOFF + lm + kb * WO_STR + np * 16));
            uint32_t b0[2] = {r0, r1}, b1r[2] = {r2, r3};
            mma_f16(acc[0][np * 2],     a[0], b0);
            mma_f16(acc[1][np * 2],     a[1], b0);
            mma_f16(acc[0][np * 2 + 1], a[0], b1r);
            mma_f16(acc[1][np * 2 + 1], a[1], b1r);
        }
    }

    #pragma unroll
    for (int mt = 0; mt < 2; ++mt) {
        #pragma unroll
        for (int h = 0; h < 2; ++h) {
            const int rl = wm * 32 + mt * 16 + g + h * 8;
            const size_t rowg = (size_t)(m0 + rl);
            float ss = 0.0f;
            #pragma unroll
            for (int nt = 0; nt < 8; ++nt) {
                const int c = wn * 64 + nt * 8 + tg * 2;
                float2 xv = *reinterpret_cast<const float2*>(x + rowg * 128 + c);
                float v0 = acc[mt][nt][h * 2 + 0] + xv.x;
                float v1 = acc[mt][nt][h * 2 + 1] + xv.y;
                acc[mt][nt][h * 2 + 0] = v0;
                acc[mt][nt][h * 2 + 1] = v1;
                *reinterpret_cast<float2*>(out1 + rowg * 128 + c) = make_float2(v0, v1);
                ss += v0 * v0 + v1 * v1;
            }
            ss += __shfl_xor_sync(0xffffffffu, ss, 1);
            ss += __shfl_xor_sync(0xffffffffu, ss, 2);
            if (tg == 0) atomicAdd(&rowss[rl], ss);
        }
    }
    __syncthreads();

    #pragma unroll
    for (int mt = 0; mt < 2; ++mt) {
        #pragma unroll
        for (int h = 0; h < 2; ++h) {
            const int rl = wm * 32 + mt * 16 + g + h * 8;
            const size_t rowg = (size_t)(m0 + rl);
            const float sc = rsqrtf(rowss[rl] * (1.0f / 128.0f) + 1e-6f);
            #pragma unroll
            for (int nt = 0; nt < 8; ++nt) {
                const int c = wn * 64 + nt * 8 + tg * 2;
                float2 gp = *reinterpret_cast<const float2*>(gpost + c);
                __half2 hv = __floats2half2_rn(acc[mt][nt][h * 2 + 0] * sc * gp.x,
                                               acc[mt][nt][h * 2 + 1] * sc * gp.y);
                *reinterpret_cast<uint32_t*>(g_h2h + rowg * 128 + c) =
                    *reinterpret_cast<uint32_t*>(&hv);
            }
        }
    }
}

// ---------------------------------------------------------------------------
// FF1 (fp16 resident)
// ---------------------------------------------------------------------------
#define F1_ASTR 136
#define F1_BOFF 17408
#define F1_BSTR 72
#define F1_SMEM ((F1_BOFF + 128 * F1_BSTR) * 2)

__global__ __launch_bounds__(256)
void ff1_kernel(const float* __restrict__ b1) {
    extern __shared__ __half smf[];
    __half* Ah = smf;
    __half* Bh = smf + F1_BOFF;
    const uint32_t smb = smem_u32(smf);

    const int m0 = blockIdx.x * 128;
    const int n0 = blockIdx.y * 64;
    const int tid = threadIdx.x, lane = tid & 31, warp = tid >> 5;
    const int wm = warp >> 1, wn = warp & 1;
    const int g = lane >> 2, tg = lane & 3;
    const int lr = lane & 7, sel = lane >> 3;

    #pragma unroll
    for (int i = 0; i < 8; i++) {
        int id = tid + i * 256;
        int m = id >> 4, c = (id & 15) << 3;
        cp16(Ah + m * F1_ASTR + c, g_h2h + (size_t)(m0 + m) * 128 + c);
    }
    #pragma unroll
    for (int i = 0; i < 4; i++) {
        int id = tid + i * 256;
        int k = id >> 3, c = (id & 7) << 3;
        cp16(Bh + k * F1_BSTR + c, g_W1h + (size_t)k * FFD + n0 + c);
    }
    cp_commit();
    cp_wait0();
    __syncthreads();

    uint32_t aoff[2];
    #pragma unroll
    for (int mt = 0; mt < 2; ++mt)
        aoff[mt] = (uint32_t)((wm * 32 + mt * 16 + (sel & 1) * 8 + lr) * F1_ASTR +
                              (sel >> 1) * 8);
    const uint32_t lm = (uint32_t)((lane & 15) * F1_BSTR + wn * 32 + ((lane >> 4) << 3));

    float acc[2][4][4];
    #pragma unroll
    for (int i = 0; i < 2; i++)
        #pragma unroll
        for (int j = 0; j < 4; j++)
            #pragma unroll
            for (int r = 0; r < 4; r++) acc[i][j][r] = 0.0f;

    #pragma unroll
    for (int kb = 0; kb < 128; kb += 16) {
        uint32_t a[2][4];
        #pragma unroll
        for (int mt = 0; mt < 2; ++mt)
            ldmx4(a[mt][0], a[mt][1], a[mt][2], a[mt][3],
                  smb + 2u * (aoff[mt] + kb));
        #pragma unroll
        for (int np = 0; np < 2; ++np) {
            uint32_t r0, r1, r2, r3;
            ldmx4t(r0, r1, r2, r3,
                   smb + 2u * (F1_BOFF + lm + kb * F1_BSTR + np * 16));
            uint32_t b0[2] = {r0, r1}, b1r[2] = {r2, r3};
            mma_f16(acc[0][np * 2],     a[0], b0);
            mma_f16(acc[1][np * 2],     a[1], b0);
            mma_f16(acc[0][np * 2 + 1], a[0], b1r);
            mma_f16(acc[1][np * 2 + 1], a[1], b1r);
        }
    }

    #pragma unroll
    for (int mt = 0; mt < 2; ++mt) {
        #pragma unroll
        for (int nt = 0; nt < 4; ++nt) {
            const int col = n0 + wn * 32 + nt * 8 + tg * 2;
            const float bb0 = b1[col], bb1 = b1[col + 1];
            #pragma unroll
            for (int h = 0; h < 2; ++h) {
                const int row = m0 + wm * 32 + mt * 16 + g + h * 8;
                float v0 = fmaxf(acc[mt][nt][h * 2 + 0] + bb0, 0.0f);
                float v1 = fmaxf(acc[mt][nt][h * 2 + 1] + bb1, 0.0f);
                __half2 hv = __floats2half2_rn(v0, v1);
                *reinterpret_cast<uint32_t*>(g_th + (size_t)row * FFD + col) =
                    *reinterpret_cast<uint32_t*>(&hv);
            }
        }
    }
}

// ---------------------------------------------------------------------------
// FF2 (fp16, BK=64 double-buffered)
// ---------------------------------------------------------------------------
#define F2_ASTR 72
#define F2_ABUF 9216
#define F2_BSTR 136
#define F2_BBUF 8704
#define F2_STAGE (F2_ABUF + F2_BBUF)
#define F2_SMEM (2 * F2_STAGE * 2)

__global__ __launch_bounds__(256)
void ff2_kernel(const float* __restrict__ b2, const float* __restrict__ res,
                float* __restrict__ out) {
    extern __shared__ __half smf[];
    const uint32_t smb = smem_u32(smf);

    const int m0 = blockIdx.x * 128;
    const int tid = threadIdx.x, lane = tid & 31, warp = tid >> 5;
    const int wm = warp >> 1, wn = warp & 1;
    const int g = lane >> 2, tg = lane & 3;
    const int lr = lane & 7, sel = lane >> 3;

    auto cpTile = [&](int stage, int k0) {
        __half* As = smf + stage * F2_STAGE;
        __half* Bs = As + F2_ABUF;
        #pragma unroll
        for (int i = 0; i < 4; i++) {
            int id = tid + i * 256;
            int m = id >> 3, c = (id & 7) << 3;
            cp16(As + m * F2_ASTR + c, g_th + (size_t)(m0 + m) * FFD + k0 + c);
        }
        #pragma unroll
        for (int i = 0; i < 4; i++) {
            int id = tid + i * 256;
            int k = id >> 4, c = (id & 15) << 3;
            cp16(Bs + k * F2_BSTR + c, g_W2h + (size_t)(k0 + k) * EDIM + c);
        }
    };

    uint32_t aoff[2];
    #pragma unroll
    for (int mt = 0; mt < 2; ++mt)
        aoff[mt] = (uint32_t)((wm * 32 + mt * 16 + (sel & 1) * 8 + lr) * F2_ASTR +
                              (sel >> 1) * 8);
    const uint32_t lm = (uint32_t)((lane & 15) * F2_BSTR + wn * 64 + ((lane >> 4) << 3));

    float acc[2][8][4];
    #pragma unroll
    for (int i = 0; i < 2; i++)
        #pragma unroll
        for (int j = 0; j < 8; j++)
            #pragma unroll
            for (int r = 0; r < 4; r++) acc[i][j][r] = 0.0f;

    cpTile(0, 0);
    cp_commit();

    for (int kt = 0; kt < 8; ++kt) {
        const int stage = kt & 1;
        if (kt + 1 < 8) { cpTile(stage ^ 1, (kt + 1) * 64); cp_commit(); cp_wait1(); }
        else            { cp_wait0(); }
        __syncthreads();
        const uint32_t abase = smb + 2u * (stage * F2_STAGE);
        const uint32_t bbase = smb + 2u * (stage * F2_STAGE + F2_ABUF + lm);
        #pragma unroll
        for (int ks = 0; ks < 4; ++ks) {
            const int kb = ks * 16;
            uint32_t a[2][4];
            #pragma unroll
            for (int mt = 0; mt < 2; ++mt)
                ldmx4(a[mt][0], a[mt][1], a[mt][2], a[mt][3],
                      abase + 2u * (aoff[mt] + kb));
            #pragma unroll
            for (int np = 0; np < 4; ++np) {
                uint32_t r0, r1, r2, r3;
                ldmx4t(r0, r1, r2, r3, bbase + 2u * (kb * F2_BSTR + np * 16));
                uint32_t b0[2] = {r0, r1}, b1r[2] = {r2, r3};
                mma_f16(acc[0][np * 2],     a[0], b0);
                mma_f16(acc[1][np * 2],     a[1], b0);
                mma_f16(acc[0][np * 2 + 1], a[0], b1r);
                mma_f16(acc[1][np * 2 + 1], a[1], b1r);
            }
        }
        __syncthreads();
    }

    #pragma unroll
    for (int mt = 0; mt < 2; ++mt) {
        #pragma unroll
        for (int nt = 0; nt < 8; ++nt) {
            const int col = wn * 64 + nt * 8 + tg * 2;
            const float bb0 = b2[col], bb1 = b2[col + 1];
            #pragma unroll
            for (int h = 0; h < 2; ++h) {
                const int row = m0 + wm * 32 + mt * 16 + g + h * 8;
                float v0 = acc[mt][nt][h * 2 + 0] + bb0 + res[(size_t)row * 128 + col];
                float v1 = acc[mt][nt][h * 2 + 1] + bb1 + res[(size_t)row * 128 + col + 1];
                out[(size_t)row * 128 + col]     = v0;
                out[(size_t)row * 128 + col + 1] = v1;
            }
        }
    }
}

// ---------------- launch ----------------
extern "C" void kernel_launch(void* const* d_in, const int* in_sizes, int n_in,
                              void* d_out, int out_size) {
    const float* x     = (const float*)d_in[0];
    const float* dis   = (const float*)d_in[1];
    const float* g_in  = (const float*)d_in[2];
    const float* g_po  = (const float*)d_in[3];
    const float* Wq    = (const float*)d_in[4];
    const float* Wk    = (const float*)d_in[5];
    const float* Wv    = (const float*)d_in[6];
    const float* alpha = (const float*)d_in[7];
    const float* Wo    = (const float*)d_in[8];
    const float* W1    = (const float*)d_in[9];
    const float* b1    = (const float*)d_in[10];
    const float* W2    = (const float*)d_in[11];
    const float* b2    = (const float*)d_in[12];
    float* out = (float*)d_out;

    float *p_h, *p_out1;
    cudaGetSymbolAddress((void**)&p_h,    g_h);
    cudaGetSymbolAddress((void**)&p_out1, g_out1);

    cudaFuncSetAttribute(big_kernel,
                         cudaFuncAttributeMaxDynamicSharedMemorySize, BIG_SMEM);
    cudaFuncSetAttribute(qkv_kernel,
                         cudaFuncAttributeMaxDynamicSharedMemorySize, QKV_SMEM);
    cudaFuncSetAttribute(wo_norm_kernel,
                         cudaFuncAttributeMaxDynamicSharedMemorySize, WO_SMEM);
    cudaFuncSetAttribute(ff1_kernel,
                         cudaFuncAttributeMaxDynamicSharedMemorySize, F1_SMEM);
    cudaFuncSetAttribute(ff2_kernel,
                         cudaFuncAttributeMaxDynamicSharedMemorySize, F2_SMEM);

    // rmsnorm (blocks 0..2047) + weight packing (blocks 2048..2303) in one launch
    prep_kernel<<<2304, 256>>>(x, g_in, p_h, W1, W2, Wo);
    qkv_kernel<<<dim3(NTOK / 128, 4), 256, QKV_SMEM>>>(p_h, Wq, Wk, Wv);
    big_kernel<<<dim3(NSEQ / 128, NB), 512, BIG_SMEM>>>(dis, alpha);
    wo_norm_kernel<<<NTOK / 128, 256, WO_SMEM>>>(x, g_po, p_out1);
    ff1_kernel<<<dim3(NTOK / 128, 8), 256, F1_SMEM>>>(b1);
    ff2_kernel<<<NTOK / 128, 256, F2_SMEM>>>(b2, p_out1, out);
}

// round 14
// speedup vs baseline: 1.1678x; 1.0082x over previous
#include <cuda_runtime.h>
#include <cuda_fp16.h>
#include <cstdint>
#include <cstddef>

#define NB     4
#define NSEQ   4096
#define EDIM   128
#define FFD    512
#define NTOK   (NB * NSEQ)

// ---------------- scratch ----------------
__device__ float  g_h   [NTOK * EDIM];
__device__ float  g_S   [NTOK * EDIM];
__device__ __half g_Xh  [NTOK * 256];
__device__ __half g_atth[NTOK * EDIM];
__device__ float  g_out1[NTOK * EDIM];
__device__ __half g_h2h [NTOK * EDIM];
__device__ __half g_th  [NTOK * FFD];
__device__ __half g_W1h [EDIM * FFD];
__device__ __half g_W2h [FFD * EDIM];
__device__ __half g_Woh [EDIM * EDIM];

// ---------------- helpers ----------------
__device__ __forceinline__ float tf32r(float x) {
    uint32_t u;
    asm("cvt.rna.tf32.f32 %0, %1;" : "=r"(u) : "f"(x));
    return __uint_as_float(u);
}
__device__ __forceinline__ void mma_tf32(float* c, const float* a, const float* b) {
    asm volatile(
        "mma.sync.aligned.m16n8k8.row.col.f32.tf32.tf32.f32 "
        "{%0,%1,%2,%3}, {%4,%5,%6,%7}, {%8,%9}, {%0,%1,%2,%3};\n"
        : "+f"(c[0]), "+f"(c[1]), "+f"(c[2]), "+f"(c[3])
        : "r"(__float_as_uint(a[0])), "r"(__float_as_uint(a[1])),
          "r"(__float_as_uint(a[2])), "r"(__float_as_uint(a[3])),
          "r"(__float_as_uint(b[0])), "r"(__float_as_uint(b[1])));
}
__device__ __forceinline__ void mma_f16(float* c, const uint32_t* a, const uint32_t* b) {
    asm volatile(
        "mma.sync.aligned.m16n8k16.row.col.f32.f16.f16.f32 "
        "{%0,%1,%2,%3}, {%4,%5,%6,%7}, {%8,%9}, {%0,%1,%2,%3};\n"
        : "+f"(c[0]), "+f"(c[1]), "+f"(c[2]), "+f"(c[3])
        : "r"(a[0]), "r"(a[1]), "r"(a[2]), "r"(a[3]), "r"(b[0]), "r"(b[1]));
}
__device__ __forceinline__ void cp16(void* s, const void* gp) {
    uint32_t sa = (uint32_t)__cvta_generic_to_shared(s);
    asm volatile("cp.async.cg.shared.global [%0], [%1], 16;\n" :: "r"(sa), "l"(gp));
}
__device__ __forceinline__ void cp_commit() {
    asm volatile("cp.async.commit_group;\n" ::: "memory");
}
__device__ __forceinline__ void cp_wait0() {
    asm volatile("cp.async.wait_group 0;\n" ::: "memory");
}
__device__ __forceinline__ void cp_wait1() {
    asm volatile("cp.async.wait_group 1;\n" ::: "memory");
}
__device__ __forceinline__ void ldmx4(uint32_t& r0, uint32_t& r1, uint32_t& r2,
                                      uint32_t& r3, uint32_t addr) {
    asm volatile("ldmatrix.sync.aligned.m8n8.x4.shared.b16 {%0,%1,%2,%3}, [%4];"
                 : "=r"(r0), "=r"(r1), "=r"(r2), "=r"(r3) : "r"(addr));
}
__device__ __forceinline__ void ldmx4t(uint32_t& r0, uint32_t& r1, uint32_t& r2,
                                       uint32_t& r3, uint32_t addr) {
    asm volatile("ldmatrix.sync.aligned.m8n8.x4.trans.shared.b16 {%0,%1,%2,%3}, [%4];"
                 : "=r"(r0), "=r"(r1), "=r"(r2), "=r"(r3) : "r"(addr));
}
__device__ __forceinline__ uint32_t smem_u32(const void* p) {
    return (uint32_t)__cvta_generic_to_shared(p);
}

// ---------------------------------------------------------------------------
// Prep: blocks [0, 2048): rmsnorm(x) -> g_h ; blocks [2048, 2304): pack weights
// ---------------------------------------------------------------------------
__global__ void prep_kernel(const float* __restrict__ x,
                            const float* __restrict__ gw,
                            float* __restrict__ y,
                            const float* __restrict__ W1,
                            const float* __restrict__ W2,
                            const float* __restrict__ Wo) {
    if (blockIdx.x < 2048) {
        int warp = (blockIdx.x * blockDim.x + threadIdx.x) >> 5;
        int lane = threadIdx.x & 31;
        float4 v = reinterpret_cast<const float4*>(x + (size_t)warp * EDIM)[lane];
        float ss = v.x * v.x + v.y * v.y + v.z * v.z + v.w * v.w;
        #pragma unroll
        for (int o = 16; o > 0; o >>= 1) ss += __shfl_xor_sync(0xffffffffu, ss, o);
        float s = rsqrtf(ss * (1.0f / 128.0f) + 1e-6f);
        float4 g4 = reinterpret_cast<const float4*>(gw)[lane];
        float4 o4 = make_float4(v.x * s * g4.x, v.y * s * g4.y,
                                v.z * s * g4.z, v.w * s * g4.w);
        reinterpret_cast<float4*>(y + (size_t)warp * EDIM)[lane] = o4;
    } else {
        int i = (blockIdx.x - 2048) * blockDim.x + threadIdx.x;
        g_W1h[i] = __float2half(W1[i]);
        g_W2h[i] = __float2half(W2[i]);
        if (i < EDIM * EDIM) g_Woh[i] = __float2half(Wo[i]);
    }
}

// ---------------------------------------------------------------------------
// Fused QKV GEMM (cp.async double-buffered) — unchanged
// ---------------------------------------------------------------------------
#define QK_A   4608
#define QK_B   1152
#define QK_BUF (QK_A + 3 * QK_B)
#define QKV_SMEM (2 * QK_BUF * 4)

__global__ __launch_bounds__(256)
void qkv_kernel(const float* __restrict__ h, const float* __restrict__ Wq,
                const float* __restrict__ Wk, const float* __restrict__ Wv) {
    extern __shared__ float smq[];
    const int m0 = blockIdx.x * 128;
    const int j0 = blockIdx.y * 32;
    const int tid = threadIdx.x, lane = tid & 31, warp = tid >> 5;
    const int wm = warp >> 1, wn = warp & 1;
    const int g = lane >> 2, tg = lane & 3;

    const float* Wp[3] = {Wq, Wk, Wv};

    auto cpTile = [&](int buf, int k0) {
        float* As = smq + buf * QK_BUF;
        #pragma unroll
        for (int i = 0; i < 4; i++) {
            int id = tid + i * 256;
            int m = id >> 3, c = (id & 7) << 2;
            cp16(As + m * 36 + c, h + (size_t)(m0 + m) * 128 + k0 + c);
        }
        int k = tid >> 3, c = (tid & 7) << 2;
        #pragma unroll
        for (int w = 0; w < 3; w++)
            cp16(As + QK_A + w * QK_B + k * 36 + c,
                 Wp[w] + (size_t)(k0 + k) * 128 + j0 + c);
    };

    float acc[3][2][2][4];
    #pragma unroll
    for (int w = 0; w < 3; w++)
        #pragma unroll
        for (int i = 0; i < 2; i++)
            #pragma unroll
            for (int j = 0; j < 2; j++)
                #pragma unroll
                for (int r = 0; r < 4; r++) acc[w][i][j][r] = 0.0f;

    cpTile(0, 0);
    cp_commit();

    for (int kt = 0; kt < 4; ++kt) {
        const int buf = kt & 1;
        if (kt + 1 < 4) { cpTile(buf ^ 1, (kt + 1) * 32); cp_commit(); cp_wait1(); }
        else            { cp_wait0(); }
        __syncthreads();
        const float* As = smq + buf * QK_BUF;
        const float* Bs = As + QK_A;
        #pragma unroll
        for (int ks = 0; ks < 4; ++ks) {
            const int kr = ks * 8 + tg;
            float a[2][4];
            #pragma unroll
            for (int mt = 0; mt < 2; ++mt) {
                int m = wm * 32 + mt * 16 + g;
                a[mt][0] = tf32r(As[m * 36 + kr]);
                a[mt][1] = tf32r(As[(m + 8) * 36 + kr]);
                a[mt][2] = tf32r(As[m * 36 + kr + 4]);
                a[mt][3] = tf32r(As[(m + 8) * 36 + kr + 4]);
            }
            #pragma unroll
            for (int w = 0; w < 3; w++) {
                #pragma unroll
                for (int nt = 0; nt < 2; ++nt) {
                    int n = wn * 16 + nt * 8 + g;
                    float bb[2];
                    bb[0] = tf32r(Bs[w * QK_B + kr * 36 + n]);
                    bb[1] = tf32r(Bs[w * QK_B + (kr + 4) * 36 + n]);
                    mma_tf32(acc[w][0][nt], a[0], bb);
                    mma_tf32(acc[w][1][nt], a[1], bb);
                }
            }
        }
        __syncthreads();
    }

    #pragma unroll
    for (int mt = 0; mt < 2; ++mt) {
        #pragma unroll
        for (int nt = 0; nt < 2; ++nt) {
            const int col = j0 + wn * 16 + nt * 8 + tg * 2;
            #pragma unroll
            for (int hh = 0; hh < 2; ++hh) {
                const int row = m0 + wm * 32 + mt * 16 + g + hh * 8;
                float q0 = acc[0][mt][nt][hh * 2], q1 = acc[0][mt][nt][hh * 2 + 1];
                float k0v = acc[1][mt][nt][hh * 2], k1v = acc[1][mt][nt][hh * 2 + 1];
                float v0 = acc[2][mt][nt][hh * 2], v1 = acc[2][mt][nt][hh * 2 + 1];
                float2 s2 = make_float2(1.0f / (1.0f + expf(-q0)),
                                        1.0f / (1.0f + expf(-q1)));
                *reinterpret_cast<float2*>(g_S + (size_t)row * 128 + col) = s2;
                float kw0 = expf(k0v), kw1 = expf(k1v);
                __half2 h0 = __floats2half2_rn(kw0 * v0, kw0);
                __half2 h1 = __floats2half2_rn(kw1 * v1, kw1);
                uint2 u;
                u.x = *reinterpret_cast<uint32_t*>(&h0);
                u.y = *reinterpret_cast<uint32_t*>(&h1);
                *reinterpret_cast<uint2*>(g_Xh + (size_t)row * 256 + 2 * col) = u;
            }
        }
    }
}

// ---------------------------------------------------------------------------
// Big GEMM (fp16 m16n8k16) — R10 structure verbatim (127 µs; DO NOT TOUCH)
// ---------------------------------------------------------------------------
#define AH_STR 40
#define AH_BUF 5120
#define BH_STR 264
#define BH_BUF 8448
#define BH_OFF 10240
#define BIG_SMEM 71168

__global__ __launch_bounds__(512, 1)
void big_kernel(const float* __restrict__ dis, const float* __restrict__ alphap) {
    extern __shared__ __half smh[];
    __half* Ah = smh;
    __half* Bh = smh + BH_OFF;
    const uint32_t smb = smem_u32(smh);

    const int tid = threadIdx.x, lane = tid & 31, warp = tid >> 5;
    const int wm = warp >> 2, wn = warp & 3;
    const int g = lane >> 2, tg = lane & 3;
    const int b = blockIdx.y, j0 = blockIdx.x * 128;
    const float coef = 12.0f * alphap[0];
    const float* Ag = dis + (size_t)b * NSEQ * NSEQ;
    const __half* Xg = g_Xh + (size_t)b * NSEQ * 256;

    const int am = tid & 127, ar4 = (tid >> 7) << 2;

    const int lr = lane & 7, sel = lane >> 3;
    uint32_t aoff[2];
    #pragma unroll
    for (int mt = 0; mt < 2; ++mt)
        aoff[mt] = (uint32_t)((wm * 32 + mt * 16 + (sel & 1) * 8 + lr) * AH_STR +
                              (sel >> 1) * 8);
    const uint32_t lm_half = (uint32_t)((lane & 15) * BH_STR + wn * 64 + ((lane >> 4) << 3));

    float ra[2][4];
    float acc[2][8][4];
    #pragma unroll
    for (int i = 0; i < 2; i++)
        #pragma unroll
        for (int j = 0; j < 8; j++)
            #pragma unroll
            for (int r = 0; r < 4; r++) acc[i][j][r] = 0.0f;

    auto ldA = [&](int k0) {
        #pragma unroll
        for (int it = 0; it < 2; ++it) {
            const float* p = Ag + (size_t)(k0 + it * 16 + ar4) * NSEQ + j0 + am;
            ra[it][0] = p[0]; ra[it][1] = p[NSEQ];
            ra[it][2] = p[2 * NSEQ]; ra[it][3] = p[3 * NSEQ];
        }
    };
    auto stA = [&](int buf) {
        __half* base = Ah + buf * AH_BUF + am * AH_STR;
        #pragma unroll
        for (int it = 0; it < 2; ++it) {
            __half2 h01 = __floats2half2_rn(__expf(-coef * ra[it][0]),
                                            __expf(-coef * ra[it][1]));
            __half2 h23 = __floats2half2_rn(__expf(-coef * ra[it][2]),
                                            __expf(-coef * ra[it][3]));
            uint2 u;
            u.x = *reinterpret_cast<uint32_t*>(&h01);
            u.y = *reinterpret_cast<uint32_t*>(&h23);
            *reinterpret_cast<uint2*>(base + it * 16 + ar4) = u;
        }
    };
    auto cpB = [&](int stage, int k0) {
        #pragma unroll
        for (int it = 0; it < 2; ++it) {
            int ch = tid + it * 512;
            int row = ch >> 5, cc = (ch & 31) << 3;
            cp16(Bh + stage * BH_BUF + row * BH_STR + cc,
                 Xg + (size_t)(k0 + row) * 256 + cc);
        }
    };

    cpB(0, 0);  cp_commit();
    cpB(1, 32); cp_commit();
    ldA(0);
    stA(0);
    cp_wait1();
    __syncthreads();

    for (int kt = 0; kt < 128; ++kt) {
        const int sbuf = kt % 3;
        const int abuf = kt & 1;
        if (kt + 2 < 128) { cpB((kt + 2) % 3, (kt + 2) * 32); cp_commit(); }
        if (kt + 1 < 128) ldA((kt + 1) * 32);

        const uint32_t abase = smb + 2u * (abuf * AH_BUF);
        const uint32_t bbase = smb + 2u * (BH_OFF + sbuf * BH_BUF + lm_half);
        #pragma unroll
        for (int ks = 0; ks < 2; ++ks) {
            const int kb = ks * 16;
            uint32_t a[2][4];
            #pragma unroll
            for (int mt = 0; mt < 2; ++mt)
                ldmx4(a[mt][0], a[mt][1], a[mt][2], a[mt][3],
                      abase + 2u * (aoff[mt] + kb));
            #pragma unroll
            for (int np = 0; np < 4; ++np) {
                uint32_t r0, r1, r2, r3;
                ldmx4t(r0, r1, r2, r3, bbase + 2u * (kb * BH_STR + np * 16));
                uint32_t b0[2] = {r0, r1}, b1[2] = {r2, r3};
                mma_f16(acc[0][np * 2],     a[0], b0);
                mma_f16(acc[1][np * 2],     a[1], b0);
                mma_f16(acc[0][np * 2 + 1], a[0], b1);
                mma_f16(acc[1][np * 2 + 1], a[1], b1);
            }
        }
        if (kt + 1 < 128) stA(abuf ^ 1);
        cp_wait1();
        __syncthreads();
    }

    const size_t rowbase = (size_t)b * NSEQ + j0;
    #pragma unroll
    for (int mt = 0; mt < 2; ++mt) {
        const int r0 = wm * 32 + mt * 16 + g;
        #pragma unroll
        for (int nt = 0; nt < 8; ++nt) {
            const int e = wn * 32 + nt * 4 + tg;
            const size_t i0 = (rowbase + r0) * 128 + e;
            const size_t i1 = (rowbase + r0 + 8) * 128 + e;
            float a0 = g_S[i0] * __fdividef(acc[mt][nt][0], acc[mt][nt][1]);
            float a1 = g_S[i1] * __fdividef(acc[mt][nt][2], acc[mt][nt][3]);
            g_atth[i0] = __float2half(a0);
            g_atth[i1] = __float2half(a1);
        }
    }
}

// ---------------------------------------------------------------------------
// Wo (fp16 resident) + residual + fused post-rmsnorm. BM=64 (grid 256),
// 8 warps = 2m x 4n, warp tile 32m x 32n.
// ---------------------------------------------------------------------------
#define WO_STR 136
#define WO_BOFF 8704                  // 64*136 halfs (att tile)
#define WO_SMEM ((WO_BOFF + 128 * WO_STR) * 2)   // 52224 bytes

__global__ __launch_bounds__(256)
void wo_norm_kernel(const float* __restrict__ x, const float* __restrict__ gpost,
                    float* __restrict__ out1) {
    extern __shared__ __half smw[];
    __shared__ float rowss[64];
    __half* Ah = smw;
    __half* Bh = smw + WO_BOFF;
    const uint32_t smb = smem_u32(smw);

    const int m0 = blockIdx.x * 64;
    const int tid = threadIdx.x, lane = tid & 31, warp = tid >> 5;
    const int wm = warp >> 2, wn = warp & 3;   // 2m x 4n
    const int g = lane >> 2, tg = lane & 3;
    const int lr = lane & 7, sel = lane >> 3;

    // att tile: 64 x 128 halfs = 1024 cp16
    #pragma unroll
    for (int i = 0; i < 4; i++) {
        int id = tid + i * 256;
        int m = id >> 4, c = (id & 15) << 3;
        cp16(Ah + m * WO_STR + c, g_atth + (size_t)(m0 + m) * 128 + c);
    }
    // Wo: 128 x 128 halfs = 2048 cp16
    #pragma unroll
    for (int i = 0; i < 8; i++) {
        int id = tid + i * 256;
        int m = id >> 4, c = (id & 15) << 3;
        cp16(Bh + m * WO_STR + c, g_Woh + (size_t)m * 128 + c);
    }
    cp_commit();
    if (tid < 64) rowss[tid] = 0.0f;
    cp_wait0();
    __syncthreads();

    uint32_t aoff[2];
    #pragma unroll
    for (int mt = 0; mt < 2; ++mt)
        aoff[mt] = (uint32_t)((wm * 32 + mt * 16 + (sel & 1) * 8 + lr) * WO_STR +
                              (sel >> 1) * 8);
    const uint32_t lm = (uint32_t)((lane & 15) * WO_STR + wn * 32 + ((lane >> 4) << 3));

    float acc[2][4][4];
    #pragma unroll
    for (int i = 0; i < 2; i++)
        #pragma unroll
        for (int j = 0; j < 4; j++)
            #pragma unroll
            for (int r = 0; r < 4; r++) acc[i][j][r] = 0.0f;

    #pragma unroll
    for (int kb = 0; kb < 128; kb += 16) {
        uint32_t a[2][4];
        #pragma unroll
        for (int mt = 0; mt < 2; ++mt)
            ldmx4(a[mt][0], a[mt][1], a[mt][2], a[mt][3],
                  smb + 2u * (aoff[mt] + kb));
        #pragma unroll
        for (int np = 0; np < 2; ++np) {
            uint32_t r0, r1, r2, r3;
            ldmx4t(r0, r1, r2, r3,
                   smb + 2u * (WO_BOFF + lm + kb * WO_STR + np * 16));
            uint32_t b0[2] = {r0, r1}, b1r[2] = {r2, r3};
            mma_f16(acc[0][np * 2],     a[0], b0);
            mma_f16(acc[1][np * 2],     a[1], b0);
            mma_f16(acc[0][np * 2 + 1], a[0], b1r);
            mma_f16(acc[1][np * 2 + 1], a[1], b1r);
        }
    }

    // out1 = x + attWo; row sum-of-squares
    #pragma unroll
    for (int mt = 0; mt < 2; ++mt) {
        #pragma unroll
        for (int h = 0; h < 2; ++h) {
            const int rl = wm * 32 + mt * 16 + g + h * 8;
            const size_t rowg = (size_t)(m0 + rl);
            float ss = 0.0f;
            #pragma unroll
            for (int nt = 0; nt < 4; ++nt) {
                const int c = wn * 32 + nt * 8 + tg * 2;
                float2 xv = *reinterpret_cast<const float2*>(x + rowg * 128 + c);
                float v0 = acc[mt][nt][h * 2 + 0] + xv.x;
                float v1 = acc[mt][nt][h * 2 + 1] + xv.y;
                acc[mt][nt][h * 2 + 0] = v0;
                acc[mt][nt][h * 2 + 1] = v1;
                *reinterpret_cast<float2*>(out1 + rowg * 128 + c) = make_float2(v0, v1);
                ss += v0 * v0 + v1 * v1;
            }
            ss += __shfl_xor_sync(0xffffffffu, ss, 1);
            ss += __shfl_xor_sync(0xffffffffu, ss, 2);
            if (tg == 0) atomicAdd(&rowss[rl], ss);
        }
    }
    __syncthreads();

    #pragma unroll
    for (int mt = 0; mt < 2; ++mt) {
        #pragma unroll
        for (int h = 0; h < 2; ++h) {
            const int rl = wm * 32 + mt * 16 + g + h * 8;
            const size_t rowg = (size_t)(m0 + rl);
            const float sc = rsqrtf(rowss[rl] * (1.0f / 128.0f) + 1e-6f);
            #pragma unroll
            for (int nt = 0; nt < 4; ++nt) {
                const int c = wn * 32 + nt * 8 + tg * 2;
                float2 gp = *reinterpret_cast<const float2*>(gpost + c);
                __half2 hv = __floats2half2_rn(acc[mt][nt][h * 2 + 0] * sc * gp.x,
                                               acc[mt][nt][h * 2 + 1] * sc * gp.y);
                *reinterpret_cast<uint32_t*>(g_h2h + rowg * 128 + c) =
                    *reinterpret_cast<uint32_t*>(&hv);
            }
        }
    }
}

// ---------------------------------------------------------------------------
// FF1 (fp16 resident) — unchanged (grid 1024, healthy)
// ---------------------------------------------------------------------------
#define F1_ASTR 136
#define F1_BOFF 17408
#define F1_BSTR 72
#define F1_SMEM ((F1_BOFF + 128 * F1_BSTR) * 2)

__global__ __launch_bounds__(256)
void ff1_kernel(const float* __restrict__ b1) {
    extern __shared__ __half smf[];
    __half* Ah = smf;
    __half* Bh = smf + F1_BOFF;
    const uint32_t smb = smem_u32(smf);

    const int m0 = blockIdx.x * 128;
    const int n0 = blockIdx.y * 64;
    const int tid = threadIdx.x, lane = tid & 31, warp = tid >> 5;
    const int wm = warp >> 1, wn = warp & 1;
    const int g = lane >> 2, tg = lane & 3;
    const int lr = lane & 7, sel = lane >> 3;

    #pragma unroll
    for (int i = 0; i < 8; i++) {
        int id = tid + i * 256;
        int m = id >> 4, c = (id & 15) << 3;
        cp16(Ah + m * F1_ASTR + c, g_h2h + (size_t)(m0 + m) * 128 + c);
    }
    #pragma unroll
    for (int i = 0; i < 4; i++) {
        int id = tid + i * 256;
        int k = id >> 3, c = (id & 7) << 3;
        cp16(Bh + k * F1_BSTR + c, g_W1h + (size_t)k * FFD + n0 + c);
    }
    cp_commit();
    cp_wait0();
    __syncthreads();

    uint32_t aoff[2];
    #pragma unroll
    for (int mt = 0; mt < 2; ++mt)
        aoff[mt] = (uint32_t)((wm * 32 + mt * 16 + (sel & 1) * 8 + lr) * F1_ASTR +
                              (sel >> 1) * 8);
    const uint32_t lm = (uint32_t)((lane & 15) * F1_BSTR + wn * 32 + ((lane >> 4) << 3));

    float acc[2][4][4];
    #pragma unroll
    for (int i = 0; i < 2; i++)
        #pragma unroll
        for (int j = 0; j < 4; j++)
            #pragma unroll
            for (int r = 0; r < 4; r++) acc[i][j][r] = 0.0f;

    #pragma unroll
    for (int kb = 0; kb < 128; kb += 16) {
        uint32_t a[2][4];
        #pragma unroll
        for (int mt = 0; mt < 2; ++mt)
            ldmx4(a[mt][0], a[mt][1], a[mt][2], a[mt][3],
                  smb + 2u * (aoff[mt] + kb));
        #pragma unroll
        for (int np = 0; np < 2; ++np) {
            uint32_t r0, r1, r2, r3;
            ldmx4t(r0, r1, r2, r3,
                   smb + 2u * (F1_BOFF + lm + kb * F1_BSTR + np * 16));
            uint32_t b0[2] = {r0, r1}, b1r[2] = {r2, r3};
            mma_f16(acc[0][np * 2],     a[0], b0);
            mma_f16(acc[1][np * 2],     a[1], b0);
            mma_f16(acc[0][np * 2 + 1], a[0], b1r);
            mma_f16(acc[1][np * 2 + 1], a[1], b1r);
        }
    }

    #pragma unroll
    for (int mt = 0; mt < 2; ++mt) {
        #pragma unroll
        for (int nt = 0; nt < 4; ++nt) {
            const int col = n0 + wn * 32 + nt * 8 + tg * 2;
            const float bb0 = b1[col], bb1 = b1[col + 1];
            #pragma unroll
            for (int h = 0; h < 2; ++h) {
                const int row = m0 + wm * 32 + mt * 16 + g + h * 8;
                float v0 = fmaxf(acc[mt][nt][h * 2 + 0] + bb0, 0.0f);
                float v1 = fmaxf(acc[mt][nt][h * 2 + 1] + bb1, 0.0f);
                __half2 hv = __floats2half2_rn(v0, v1);
                *reinterpret_cast<uint32_t*>(g_th + (size_t)row * FFD + col) =
                    *reinterpret_cast<uint32_t*>(&hv);
            }
        }
    }
}

// ---------------------------------------------------------------------------
// FF2 (fp16): out = out1 + t @ W2 + b2. BM=64 (grid 256), BK=64 double-buffered.
// 8 warps = 2m x 4n, warp tile 32m x 32n over N=128.
// ---------------------------------------------------------------------------
#define F2_ASTR 72
#define F2_ABUF 4608                 // 64*72 halfs
#define F2_BSTR 136
#define F2_BBUF 8704                 // 64*136 halfs
#define F2_STAGE (F2_ABUF + F2_BBUF) // 13312 halfs
#define F2_SMEM (2 * F2_STAGE * 2)   // 53248 bytes

__global__ __launch_bounds__(256)
void ff2_kernel(const float* __restrict__ b2, const float* __restrict__ res,
                float* __restrict__ out) {
    extern __shared__ __half smf[];
    const uint32_t smb = smem_u32(smf);

    const int m0 = blockIdx.x * 64;
    const int tid = threadIdx.x, lane = tid & 31, warp = tid >> 5;
    const int wm = warp >> 2, wn = warp & 3;   // 2m x 4n
    const int g = lane >> 2, tg = lane & 3;
    const int lr = lane & 7, sel = lane >> 3;

    auto cpTile = [&](int stage, int k0) {
        __half* As = smf + stage * F2_STAGE;
        __half* Bs = As + F2_ABUF;
        #pragma unroll
        for (int i = 0; i < 2; i++) {
            int id = tid + i * 256;
            int m = id >> 3, c = (id & 7) << 3;
            cp16(As + m * F2_ASTR + c, g_th + (size_t)(m0 + m) * FFD + k0 + c);
        }
        #pragma unroll
        for (int i = 0; i < 4; i++) {
            int id = tid + i * 256;
            int k = id >> 4, c = (id & 15) << 3;
            cp16(Bs + k * F2_BSTR + c, g_W2h + (size_t)(k0 + k) * EDIM + c);
        }
    };

    uint32_t aoff[2];
    #pragma unroll
    for (int mt = 0; mt < 2; ++mt)
        aoff[mt] = (uint32_t)((wm * 32 + mt * 16 + (sel & 1) * 8 + lr) * F2_ASTR +
                              (sel >> 1) * 8);
    const uint32_t lm = (uint32_t)((lane & 15) * F2_BSTR + wn * 32 + ((lane >> 4) << 3));

    float acc[2][4][4];
    #pragma unroll
    for (int i = 0; i < 2; i++)
        #pragma unroll
        for (int j = 0; j < 4; j++)
            #pragma unroll
            for (int r = 0; r < 4; r++) acc[i][j][r] = 0.0f;

    cpTile(0, 0);
    cp_commit();

    for (int kt = 0; kt < 8; ++kt) {
        const int stage = kt & 1;
        if (kt + 1 < 8) { cpTile(stage ^ 1, (kt + 1) * 64); cp_commit(); cp_wait1(); }
        else            { cp_wait0(); }
        __syncthreads();
        const uint32_t abase = smb + 2u * (stage * F2_STAGE);
        const uint32_t bbase = smb + 2u * (stage * F2_STAGE + F2_ABUF + lm);
        #pragma unroll
        for (int ks = 0; ks < 4; ++ks) {
            const int kb = ks * 16;
            uint32_t a[2][4];
            #pragma unroll
            for (int mt = 0; mt < 2; ++mt)
                ldmx4(a[mt][0], a[mt][1], a[mt][2], a[mt][3],
                      abase + 2u * (aoff[mt] + kb));
            #pragma unroll
            for (int np = 0; np < 2; ++np) {
                uint32_t r0, r1, r2, r3;
                ldmx4t(r0, r1, r2, r3, bbase + 2u * (kb * F2_BSTR + np * 16));
                uint32_t b0[2] = {r0, r1}, b1r[2] = {r2, r3};
                mma_f16(acc[0][np * 2],     a[0], b0);
                mma_f16(acc[1][np * 2],     a[1], b0);
                mma_f16(acc[0][np * 2 + 1], a[0], b1r);
                mma_f16(acc[1][np * 2 + 1], a[1], b1r);
            }
        }
        __syncthreads();
    }

    #pragma unroll
    for (int mt = 0; mt < 2; ++mt) {
        #pragma unroll
        for (int nt = 0; nt < 4; ++nt) {
            const int col = wn * 32 + nt * 8 + tg * 2;
            const float bb0 = b2[col], bb1 = b2[col + 1];
            #pragma unroll
            for (int h = 0; h < 2; ++h) {
                const int row = m0 + wm * 32 + mt * 16 + g + h * 8;
                float v0 = acc[mt][nt][h * 2 + 0] + bb0 + res[(size_t)row * 128 + col];
                float v1 = acc[mt][nt][h * 2 + 1] + bb1 + res[(size_t)row * 128 + col + 1];
                out[(size_t)row * 128 + col]     = v0;
                out[(size_t)row * 128 + col + 1] = v1;
            }
        }
    }
}

// ---------------- launch ----------------
extern "C" void kernel_launch(void* const* d_in, const int* in_sizes, int n_in,
                              void* d_out, int out_size) {
    const float* x     = (const float*)d_in[0];
    const float* dis   = (const float*)d_in[1];
    const float* g_in  = (const float*)d_in[2];
    const float* g_po  = (const float*)d_in[3];
    const float* Wq    = (const float*)d_in[4];
    const float* Wk    = (const float*)d_in[5];
    const float* Wv    = (const float*)d_in[6];
    const float* alpha = (const float*)d_in[7];
    const float* Wo    = (const float*)d_in[8];
    const float* W1    = (const float*)d_in[9];
    const float* b1    = (const float*)d_in[10];
    const float* W2    = (const float*)d_in[11];
    const float* b2    = (const float*)d_in[12];
    float* out = (float*)d_out;

    float *p_h, *p_out1;
    cudaGetSymbolAddress((void**)&p_h,    g_h);
    cudaGetSymbolAddress((void**)&p_out1, g_out1);

    cudaFuncSetAttribute(big_kernel,
                         cudaFuncAttributeMaxDynamicSharedMemorySize, BIG_SMEM);
    cudaFuncSetAttribute(qkv_kernel,
                         cudaFuncAttributeMaxDynamicSharedMemorySize, QKV_SMEM);
    cudaFuncSetAttribute(wo_norm_kernel,
                         cudaFuncAttributeMaxDynamicSharedMemorySize, WO_SMEM);
    cudaFuncSetAttribute(ff1_kernel,
                         cudaFuncAttributeMaxDynamicSharedMemorySize, F1_SMEM);
    cudaFuncSetAttribute(ff2_kernel,
                         cudaFuncAttributeMaxDynamicSharedMemorySize, F2_SMEM);

    prep_kernel<<<2304, 256>>>(x, g_in, p_h, W1, W2, Wo);
    qkv_kernel<<<dim3(NTOK / 128, 4), 256, QKV_SMEM>>>(p_h, Wq, Wk, Wv);
    big_kernel<<<dim3(NSEQ / 128, NB), 512, BIG_SMEM>>>(dis, alpha);
    wo_norm_kernel<<<NTOK / 64, 256, WO_SMEM>>>(x, g_po, p_out1);
    ff1_kernel<<<dim3(NTOK / 128, 8), 256, F1_SMEM>>>(b1);
    ff2_kernel<<<NTOK / 64, 256, F2_SMEM>>>(b2, p_out1, out);
}

// round 15
// speedup vs baseline: 1.2325x; 1.0554x over previous
#include <cuda_runtime.h>
#include <cuda_fp16.h>
#include <cstdint>
#include <cstddef>

#define NB     4
#define NSEQ   4096
#define EDIM   128
#define FFD    512
#define NTOK   (NB * NSEQ)

// ---------------- scratch ----------------
__device__ __half g_hh  [NTOK * EDIM];
__device__ float  g_S   [NTOK * EDIM];
__device__ __half g_Xh  [NTOK * 256];
__device__ __half g_atth[NTOK * EDIM];
__device__ float  g_out1[NTOK * EDIM];
__device__ __half g_h2h [NTOK * EDIM];
__device__ __half g_th  [NTOK * FFD];
__device__ __half g_W1h [EDIM * FFD];
__device__ __half g_W2h [FFD * EDIM];
__device__ __half g_Woh [EDIM * EDIM];
__device__ __half g_Wqh [EDIM * EDIM];
__device__ __half g_Wkh [EDIM * EDIM];
__device__ __half g_Wvh [EDIM * EDIM];

// ---------------- helpers ----------------
__device__ __forceinline__ void mma_f16(float* c, const uint32_t* a, const uint32_t* b) {
    asm volatile(
        "mma.sync.aligned.m16n8k16.row.col.f32.f16.f16.f32 "
        "{%0,%1,%2,%3}, {%4,%5,%6,%7}, {%8,%9}, {%0,%1,%2,%3};\n"
        : "+f"(c[0]), "+f"(c[1]), "+f"(c[2]), "+f"(c[3])
        : "r"(a[0]), "r"(a[1]), "r"(a[2]), "r"(a[3]), "r"(b[0]), "r"(b[1]));
}
__device__ __forceinline__ void cp16(void* s, const void* gp) {
    uint32_t sa = (uint32_t)__cvta_generic_to_shared(s);
    asm volatile("cp.async.cg.shared.global [%0], [%1], 16;\n" :: "r"(sa), "l"(gp));
}
__device__ __forceinline__ void cp_commit() {
    asm volatile("cp.async.commit_group;\n" ::: "memory");
}
__device__ __forceinline__ void cp_wait0() {
    asm volatile("cp.async.wait_group 0;\n" ::: "memory");
}
__device__ __forceinline__ void cp_wait1() {
    asm volatile("cp.async.wait_group 1;\n" ::: "memory");
}
__device__ __forceinline__ void ldmx4(uint32_t& r0, uint32_t& r1, uint32_t& r2,
                                      uint32_t& r3, uint32_t addr) {
    asm volatile("ldmatrix.sync.aligned.m8n8.x4.shared.b16 {%0,%1,%2,%3}, [%4];"
                 : "=r"(r0), "=r"(r1), "=r"(r2), "=r"(r3) : "r"(addr));
}
__device__ __forceinline__ void ldmx4t(uint32_t& r0, uint32_t& r1, uint32_t& r2,
                                       uint32_t& r3, uint32_t addr) {
    asm volatile("ldmatrix.sync.aligned.m8n8.x4.trans.shared.b16 {%0,%1,%2,%3}, [%4];"
                 : "=r"(r0), "=r"(r1), "=r"(r2), "=r"(r3) : "r"(addr));
}
__device__ __forceinline__ uint32_t smem_u32(const void* p) {
    return (uint32_t)__cvta_generic_to_shared(p);
}

// ---------------------------------------------------------------------------
// Prep: blocks [0, 2048): rmsnorm(x) -> g_hh (half);
//       blocks [2048, 2304): pack W1/W2/Wo/Wq/Wk/Wv to half
// ---------------------------------------------------------------------------
__global__ void prep_kernel(const float* __restrict__ x,
                            const float* __restrict__ gw,
                            const float* __restrict__ W1,
                            const float* __restrict__ W2,
                            const float* __restrict__ Wo,
                            const float* __restrict__ Wq,
                            const float* __restrict__ Wk,
                            const float* __restrict__ Wv) {
    if (blockIdx.x < 2048) {
        int warp = (blockIdx.x * blockDim.x + threadIdx.x) >> 5;
        int lane = threadIdx.x & 31;
        float4 v = reinterpret_cast<const float4*>(x + (size_t)warp * EDIM)[lane];
        float ss = v.x * v.x + v.y * v.y + v.z * v.z + v.w * v.w;
        #pragma unroll
        for (int o = 16; o > 0; o >>= 1) ss += __shfl_xor_sync(0xffffffffu, ss, o);
        float s = rsqrtf(ss * (1.0f / 128.0f) + 1e-6f);
        float4 g4 = reinterpret_cast<const float4*>(gw)[lane];
        __half2 h0 = __floats2half2_rn(v.x * s * g4.x, v.y * s * g4.y);
        __half2 h1 = __floats2half2_rn(v.z * s * g4.z, v.w * s * g4.w);
        uint2 u;
        u.x = *reinterpret_cast<uint32_t*>(&h0);
        u.y = *reinterpret_cast<uint32_t*>(&h1);
        *reinterpret_cast<uint2*>(g_hh + (size_t)warp * EDIM + lane * 4) = u;
    } else {
        int i = (blockIdx.x - 2048) * blockDim.x + threadIdx.x;
        g_W1h[i] = __float2half(W1[i]);
        g_W2h[i] = __float2half(W2[i]);
        if (i < EDIM * EDIM) {
            g_Woh[i] = __float2half(Wo[i]);
            g_Wqh[i] = __float2half(Wq[i]);
            g_Wkh[i] = __float2half(Wk[i]);
            g_Wvh[i] = __float2half(Wv[i]);
        }
    }
}

// ---------------------------------------------------------------------------
// QKV (fp16, K=128 resident, one sync): block = 128 tokens x 32 cols of q,k,v.
// A: [128][136]h, B[w]: [128][40]h ([k][n], stride 40 = conflict-free trans).
// Epilogue: g_S = sigmoid(q); g_Xh = interleaved (exp(k)*v, exp(k)) half pairs.
// ---------------------------------------------------------------------------
#define Q2_ASTR 136
#define Q2_BOFF 17408                 // 128*136 halfs
#define Q2_BSTR 40
#define Q2_BBUF 5120                  // 128*40 halfs per weight
#define QKV_SMEM ((Q2_BOFF + 3 * Q2_BBUF) * 2)   // 65536 bytes

__global__ __launch_bounds__(256)
void qkv_kernel() {
    extern __shared__ __half smq[];
    __half* Ah = smq;
    __half* Bh = smq + Q2_BOFF;
    const uint32_t smb = smem_u32(smq);

    const int m0 = blockIdx.x * 128;
    const int j0 = blockIdx.y * 32;
    const int tid = threadIdx.x, lane = tid & 31, warp = tid >> 5;
    const int wm = warp >> 1, wn = warp & 1;     // 4m x 2n; warp 32m x 16n per weight
    const int g = lane >> 2, tg = lane & 3;
    const int lr = lane & 7, sel = lane >> 3;

    const __half* Wh[3] = {g_Wqh, g_Wkh, g_Wvh};

    // A: 128x128 half = 2048 cp16 (8/thread)
    #pragma unroll
    for (int i = 0; i < 8; i++) {
        int id = tid + i * 256;
        int m = id >> 4, c = (id & 15) << 3;
        cp16(Ah + m * Q2_ASTR + c, g_hh + (size_t)(m0 + m) * 128 + c);
    }
    // B: 3 x 128x32 half = 3 x 512 cp16 (6/thread)
    #pragma unroll
    for (int w = 0; w < 3; w++) {
        #pragma unroll
        for (int i = 0; i < 2; i++) {
            int id = tid + i * 256;
            int k = id >> 2, c = (id & 3) << 3;
            cp16(Bh + w * Q2_BBUF + k * Q2_BSTR + c,
                 Wh[w] + (size_t)k * 128 + j0 + c);
        }
    }
    cp_commit();
    cp_wait0();
    __syncthreads();

    uint32_t aoff[2];
    #pragma unroll
    for (int mt = 0; mt < 2; ++mt)
        aoff[mt] = (uint32_t)((wm * 32 + mt * 16 + (sel & 1) * 8 + lr) * Q2_ASTR +
                              (sel >> 1) * 8);
    const uint32_t lmB = (uint32_t)((lane & 15) * Q2_BSTR + wn * 16 + ((lane >> 4) << 3));

    float acc[3][2][2][4];
    #pragma unroll
    for (int w = 0; w < 3; w++)
        #pragma unroll
        for (int i = 0; i < 2; i++)
            #pragma unroll
            for (int j = 0; j < 2; j++)
                #pragma unroll
                for (int r = 0; r < 4; r++) acc[w][i][j][r] = 0.0f;

    #pragma unroll
    for (int kb = 0; kb < 128; kb += 16) {
        uint32_t a[2][4];
        #pragma unroll
        for (int mt = 0; mt < 2; ++mt)
            ldmx4(a[mt][0], a[mt][1], a[mt][2], a[mt][3],
                  smb + 2u * (aoff[mt] + kb));
        #pragma unroll
        for (int w = 0; w < 3; w++) {
            uint32_t r0, r1, r2, r3;
            ldmx4t(r0, r1, r2, r3,
                   smb + 2u * (Q2_BOFF + w * Q2_BBUF + lmB + kb * Q2_BSTR));
            uint32_t b0[2] = {r0, r1}, b1[2] = {r2, r3};
            mma_f16(acc[w][0][0], a[0], b0);
            mma_f16(acc[w][1][0], a[1], b0);
            mma_f16(acc[w][0][1], a[0], b1);
            mma_f16(acc[w][1][1], a[1], b1);
        }
    }

    // epilogue: sigmoid(q) -> g_S ; interleaved (exp(k)*v, exp(k)) -> g_Xh
    #pragma unroll
    for (int mt = 0; mt < 2; ++mt) {
        #pragma unroll
        for (int nt = 0; nt < 2; ++nt) {
            const int col = j0 + wn * 16 + nt * 8 + tg * 2;
            #pragma unroll
            for (int hh = 0; hh < 2; ++hh) {
                const int row = m0 + wm * 32 + mt * 16 + g + hh * 8;
                float q0 = acc[0][mt][nt][hh * 2], q1 = acc[0][mt][nt][hh * 2 + 1];
                float k0v = acc[1][mt][nt][hh * 2], k1v = acc[1][mt][nt][hh * 2 + 1];
                float v0 = acc[2][mt][nt][hh * 2], v1 = acc[2][mt][nt][hh * 2 + 1];
                float2 s2 = make_float2(1.0f / (1.0f + expf(-q0)),
                                        1.0f / (1.0f + expf(-q1)));
                *reinterpret_cast<float2*>(g_S + (size_t)row * 128 + col) = s2;
                float kw0 = expf(k0v), kw1 = expf(k1v);
                __half2 h0 = __floats2half2_rn(kw0 * v0, kw0);
                __half2 h1 = __floats2half2_rn(kw1 * v1, kw1);
                uint2 u;
                u.x = *reinterpret_cast<uint32_t*>(&h0);
                u.y = *reinterpret_cast<uint32_t*>(&h1);
                *reinterpret_cast<uint2*>(g_Xh + (size_t)row * 256 + 2 * col) = u;
            }
        }
    }
}

// ---------------------------------------------------------------------------
// Big GEMM (fp16 m16n8k16) — R10 structure verbatim (127 µs; DO NOT TOUCH)
// ---------------------------------------------------------------------------
#define AH_STR 40
#define AH_BUF 5120
#define BH_STR 264
#define BH_BUF 8448
#define BH_OFF 10240
#define BIG_SMEM 71168

__global__ __launch_bounds__(512, 1)
void big_kernel(const float* __restrict__ dis, const float* __restrict__ alphap) {
    extern __shared__ __half smh[];
    __half* Ah = smh;
    __half* Bh = smh + BH_OFF;
    const uint32_t smb = smem_u32(smh);

    const int tid = threadIdx.x, lane = tid & 31, warp = tid >> 5;
    const int wm = warp >> 2, wn = warp & 3;
    const int g = lane >> 2, tg = lane & 3;
    const int b = blockIdx.y, j0 = blockIdx.x * 128;
    const float coef = 12.0f * alphap[0];
    const float* Ag = dis + (size_t)b * NSEQ * NSEQ;
    const __half* Xg = g_Xh + (size_t)b * NSEQ * 256;

    const int am = tid & 127, ar4 = (tid >> 7) << 2;

    const int lr = lane & 7, sel = lane >> 3;
    uint32_t aoff[2];
    #pragma unroll
    for (int mt = 0; mt < 2; ++mt)
        aoff[mt] = (uint32_t)((wm * 32 + mt * 16 + (sel & 1) * 8 + lr) * AH_STR +
                              (sel >> 1) * 8);
    const uint32_t lm_half = (uint32_t)((lane & 15) * BH_STR + wn * 64 + ((lane >> 4) << 3));

    float ra[2][4];
    float acc[2][8][4];
    #pragma unroll
    for (int i = 0; i < 2; i++)
        #pragma unroll
        for (int j = 0; j < 8; j++)
            #pragma unroll
            for (int r = 0; r < 4; r++) acc[i][j][r] = 0.0f;

    auto ldA = [&](int k0) {
        #pragma unroll
        for (int it = 0; it < 2; ++it) {
            const float* p = Ag + (size_t)(k0 + it * 16 + ar4) * NSEQ + j0 + am;
            ra[it][0] = p[0]; ra[it][1] = p[NSEQ];
            ra[it][2] = p[2 * NSEQ]; ra[it][3] = p[3 * NSEQ];
        }
    };
    auto stA = [&](int buf) {
        __half* base = Ah + buf * AH_BUF + am * AH_STR;
        #pragma unroll
        for (int it = 0; it < 2; ++it) {
            __half2 h01 = __floats2half2_rn(__expf(-coef * ra[it][0]),
                                            __expf(-coef * ra[it][1]));
            __half2 h23 = __floats2half2_rn(__expf(-coef * ra[it][2]),
                                            __expf(-coef * ra[it][3]));
            uint2 u;
            u.x = *reinterpret_cast<uint32_t*>(&h01);
            u.y = *reinterpret_cast<uint32_t*>(&h23);
            *reinterpret_cast<uint2*>(base + it * 16 + ar4) = u;
        }
    };
    auto cpB = [&](int stage, int k0) {
        #pragma unroll
        for (int it = 0; it < 2; ++it) {
            int ch = tid + it * 512;
            int row = ch >> 5, cc = (ch & 31) << 3;
            cp16(Bh + stage * BH_BUF + row * BH_STR + cc,
                 Xg + (size_t)(k0 + row) * 256 + cc);
        }
    };

    cpB(0, 0);  cp_commit();
    cpB(1, 32); cp_commit();
    ldA(0);
    stA(0);
    cp_wait1();
    __syncthreads();

    for (int kt = 0; kt < 128; ++kt) {
        const int sbuf = kt % 3;
        const int abuf = kt & 1;
        if (kt + 2 < 128) { cpB((kt + 2) % 3, (kt + 2) * 32); cp_commit(); }
        if (kt + 1 < 128) ldA((kt + 1) * 32);

        const uint32_t abase = smb + 2u * (abuf * AH_BUF);
        const uint32_t bbase = smb + 2u * (BH_OFF + sbuf * BH_BUF + lm_half);
        #pragma unroll
        for (int ks = 0; ks < 2; ++ks) {
            const int kb = ks * 16;
            uint32_t a[2][4];
            #pragma unroll
            for (int mt = 0; mt < 2; ++mt)
                ldmx4(a[mt][0], a[mt][1], a[mt][2], a[mt][3],
                      abase + 2u * (aoff[mt] + kb));
            #pragma unroll
            for (int np = 0; np < 4; ++np) {
                uint32_t r0, r1, r2, r3;
                ldmx4t(r0, r1, r2, r3, bbase + 2u * (kb * BH_STR + np * 16));
                uint32_t b0[2] = {r0, r1}, b1[2] = {r2, r3};
                mma_f16(acc[0][np * 2],     a[0], b0);
                mma_f16(acc[1][np * 2],     a[1], b0);
                mma_f16(acc[0][np * 2 + 1], a[0], b1);
                mma_f16(acc[1][np * 2 + 1], a[1], b1);
            }
        }
        if (kt + 1 < 128) stA(abuf ^ 1);
        cp_wait1();
        __syncthreads();
    }

    const size_t rowbase = (size_t)b * NSEQ + j0;
    #pragma unroll
    for (int mt = 0; mt < 2; ++mt) {
        const int r0 = wm * 32 + mt * 16 + g;
        #pragma unroll
        for (int nt = 0; nt < 8; ++nt) {
            const int e = wn * 32 + nt * 4 + tg;
            const size_t i0 = (rowbase + r0) * 128 + e;
            const size_t i1 = (rowbase + r0 + 8) * 128 + e;
            float a0 = g_S[i0] * __fdividef(acc[mt][nt][0], acc[mt][nt][1]);
            float a1 = g_S[i1] * __fdividef(acc[mt][nt][2], acc[mt][nt][3]);
            g_atth[i0] = __float2half(a0);
            g_atth[i1] = __float2half(a1);
        }
    }
}

// ---------------------------------------------------------------------------
// Wo (fp16 resident) + residual + fused post-rmsnorm. BM=64 (grid 256).
// ---------------------------------------------------------------------------
#define WO_STR 136
#define WO_BOFF 8704
#define WO_SMEM ((WO_BOFF + 128 * WO_STR) * 2)

__global__ __launch_bounds__(256)
void wo_norm_kernel(const float* __restrict__ x, const float* __restrict__ gpost,
                    float* __restrict__ out1) {
    extern __shared__ __half smw[];
    __shared__ float rowss[64];
    __half* Ah = smw;
    __half* Bh = smw + WO_BOFF;
    const uint32_t smb = smem_u32(smw);

    const int m0 = blockIdx.x * 64;
    const int tid = threadIdx.x, lane = tid & 31, warp = tid >> 5;
    const int wm = warp >> 2, wn = warp & 3;
    const int g = lane >> 2, tg = lane & 3;
    const int lr = lane & 7, sel = lane >> 3;

    #pragma unroll
    for (int i = 0; i < 4; i++) {
        int id = tid + i * 256;
        int m = id >> 4, c = (id & 15) << 3;
        cp16(Ah + m * WO_STR + c, g_atth + (size_t)(m0 + m) * 128 + c);
    }
    #pragma unroll
    for (int i = 0; i < 8; i++) {
        int id = tid + i * 256;
        int m = id >> 4, c = (id & 15) << 3;
        cp16(Bh + m * WO_STR + c, g_Woh + (size_t)m * 128 + c);
    }
    cp_commit();
    if (tid < 64) rowss[tid] = 0.0f;
    cp_wait0();
    __syncthreads();

    uint32_t aoff[2];
    #pragma unroll
    for (int mt = 0; mt < 2; ++mt)
        aoff[mt] = (uint32_t)((wm * 32 + mt * 16 + (sel & 1) * 8 + lr) * WO_STR +
                              (sel >> 1) * 8);
    const uint32_t lm = (uint32_t)((lane & 15) * WO_STR + wn * 32 + ((lane >> 4) << 3));

    float acc[2][4][4];
    #pragma unroll
    for (int i = 0; i < 2; i++)
        #pragma unroll
        for (int j = 0; j < 4; j++)
            #pragma unroll
            for (int r = 0; r < 4; r++) acc[i][j][r] = 0.0f;

    #pragma unroll
    for (int kb = 0; kb < 128; kb += 16) {
        uint32_t a[2][4];
        #pragma unroll
        for (int mt = 0; mt < 2; ++mt)
            ldmx4(a[mt][0], a[mt][1], a[mt][2], a[mt][3],
                  smb + 2u * (aoff[mt] + kb));
        #pragma unroll
        for (int np = 0; np < 2; ++np) {
            uint32_t r0, r1, r2, r3;
            ldmx4t(r0, r1, r2, r3,
                   smb + 2u * (WO_BOFF + lm + kb * WO_STR + np * 16));
            uint32_t b0[2] = {r0, r1}, b1r[2] = {r2, r3};
            mma_f16(acc[0][np * 2],     a[0], b0);
            mma_f16(acc[1][np * 2],     a[1], b0);
            mma_f16(acc[0][np * 2 + 1], a[0], b1r);
            mma_f16(acc[1][np * 2 + 1], a[1], b1r);
        }
    }

    #pragma unroll
    for (int mt = 0; mt < 2; ++mt) {
        #pragma unroll
        for (int h = 0; h < 2; ++h) {
            const int rl = wm * 32 + mt * 16 + g + h * 8;
            const size_t rowg = (size_t)(m0 + rl);
            float ss = 0.0f;
            #pragma unroll
            for (int nt = 0; nt < 4; ++nt) {
                const int c = wn * 32 + nt * 8 + tg * 2;
                float2 xv = *reinterpret_cast<const float2*>(x + rowg * 128 + c);
                float v0 = acc[mt][nt][h * 2 + 0] + xv.x;
                float v1 = acc[mt][nt][h * 2 + 1] + xv.y;
                acc[mt][nt][h * 2 + 0] = v0;
                acc[mt][nt][h * 2 + 1] = v1;
                *reinterpret_cast<float2*>(out1 + rowg * 128 + c) = make_float2(v0, v1);
                ss += v0 * v0 + v1 * v1;
            }
            ss += __shfl_xor_sync(0xffffffffu, ss, 1);
            ss += __shfl_xor_sync(0xffffffffu, ss, 2);
            if (tg == 0) atomicAdd(&rowss[rl], ss);
        }
    }
    __syncthreads();

    #pragma unroll
    for (int mt = 0; mt < 2; ++mt) {
        #pragma unroll
        for (int h = 0; h < 2; ++h) {
            const int rl = wm * 32 + mt * 16 + g + h * 8;
            const size_t rowg = (size_t)(m0 + rl);
            const float sc = rsqrtf(rowss[rl] * (1.0f / 128.0f) + 1e-6f);
            #pragma unroll
            for (int nt = 0; nt < 4; ++nt) {
                const int c = wn * 32 + nt * 8 + tg * 2;
                float2 gp = *reinterpret_cast<const float2*>(gpost + c);
                __half2 hv = __floats2half2_rn(acc[mt][nt][h * 2 + 0] * sc * gp.x,
                                               acc[mt][nt][h * 2 + 1] * sc * gp.y);
                *reinterpret_cast<uint32_t*>(g_h2h + rowg * 128 + c) =
                    *reinterpret_cast<uint32_t*>(&hv);
            }
        }
    }
}

// ---------------------------------------------------------------------------
// FF1 (fp16 resident) — unchanged
// ---------------------------------------------------------------------------
#define F1_ASTR 136
#define F1_BOFF 17408
#define F1_BSTR 72
#define F1_SMEM ((F1_BOFF + 128 * F1_BSTR) * 2)

__global__ __launch_bounds__(256)
void ff1_kernel(const float* __restrict__ b1) {
    extern __shared__ __half smf[];
    __half* Ah = smf;
    __half* Bh = smf + F1_BOFF;
    const uint32_t smb = smem_u32(smf);

    const int m0 = blockIdx.x * 128;
    const int n0 = blockIdx.y * 64;
    const int tid = threadIdx.x, lane = tid & 31, warp = tid >> 5;
    const int wm = warp >> 1, wn = warp & 1;
    const int g = lane >> 2, tg = lane & 3;
    const int lr = lane & 7, sel = lane >> 3;

    #pragma unroll
    for (int i = 0; i < 8; i++) {
        int id = tid + i * 256;
        int m = id >> 4, c = (id & 15) << 3;
        cp16(Ah + m * F1_ASTR + c, g_h2h + (size_t)(m0 + m) * 128 + c);
    }
    #pragma unroll
    for (int i = 0; i < 4; i++) {
        int id = tid + i * 256;
        int k = id >> 3, c = (id & 7) << 3;
        cp16(Bh + k * F1_BSTR + c, g_W1h + (size_t)k * FFD + n0 + c);
    }
    cp_commit();
    cp_wait0();
    __syncthreads();

    uint32_t aoff[2];
    #pragma unroll
    for (int mt = 0; mt < 2; ++mt)
        aoff[mt] = (uint32_t)((wm * 32 + mt * 16 + (sel & 1) * 8 + lr) * F1_ASTR +
                              (sel >> 1) * 8);
    const uint32_t lm = (uint32_t)((lane & 15) * F1_BSTR + wn * 32 + ((lane >> 4) << 3));

    float acc[2][4][4];
    #pragma unroll
    for (int i = 0; i < 2; i++)
        #pragma unroll
        for (int j = 0; j < 4; j++)
            #pragma unroll
            for (int r = 0; r < 4; r++) acc[i][j][r] = 0.0f;

    #pragma unroll
    for (int kb = 0; kb < 128; kb += 16) {
        uint32_t a[2][4];
        #pragma unroll
        for (int mt = 0; mt < 2; ++mt)
            ldmx4(a[mt][0], a[mt][1], a[mt][2], a[mt][3],
                  smb + 2u * (aoff[mt] + kb));
        #pragma unroll
        for (int np = 0; np < 2; ++np) {
            uint32_t r0, r1, r2, r3;
            ldmx4t(r0, r1, r2, r3,
                   smb + 2u * (F1_BOFF + lm + kb * F1_BSTR + np * 16));
            uint32_t b0[2] = {r0, r1}, b1r[2] = {r2, r3};
            mma_f16(acc[0][np * 2],     a[0], b0);
            mma_f16(acc[1][np * 2],     a[1], b0);
            mma_f16(acc[0][np * 2 + 1], a[0], b1r);
            mma_f16(acc[1][np * 2 + 1], a[1], b1r);
        }
    }

    #pragma unroll
    for (int mt = 0; mt < 2; ++mt) {
        #pragma unroll
        for (int nt = 0; nt < 4; ++nt) {
            const int col = n0 + wn * 32 + nt * 8 + tg * 2;
            const float bb0 = b1[col], bb1 = b1[col + 1];
            #pragma unroll
            for (int h = 0; h < 2; ++h) {
                const int row = m0 + wm * 32 + mt * 16 + g + h * 8;
                float v0 = fmaxf(acc[mt][nt][h * 2 + 0] + bb0, 0.0f);
                float v1 = fmaxf(acc[mt][nt][h * 2 + 1] + bb1, 0.0f);
                __half2 hv = __floats2half2_rn(v0, v1);
                *reinterpret_cast<uint32_t*>(g_th + (size_t)row * FFD + col) =
                    *reinterpret_cast<uint32_t*>(&hv);
            }
        }
    }
}

// ---------------------------------------------------------------------------
// FF2 (fp16): BM=64, BK=64 double-buffered — unchanged
// ---------------------------------------------------------------------------
#define F2_ASTR 72
#define F2_ABUF 4608
#define F2_BSTR 136
#define F2_BBUF 8704
#define F2_STAGE (F2_ABUF + F2_BBUF)
#define F2_SMEM (2 * F2_STAGE * 2)

__global__ __launch_bounds__(256)
void ff2_kernel(const float* __restrict__ b2, const float* __restrict__ res,
                float* __restrict__ out) {
    extern __shared__ __half smf[];
    const uint32_t smb = smem_u32(smf);

    const int m0 = blockIdx.x * 64;
    const int tid = threadIdx.x, lane = tid & 31, warp = tid >> 5;
    const int wm = warp >> 2, wn = warp & 3;
    const int g = lane >> 2, tg = lane & 3;
    const int lr = lane & 7, sel = lane >> 3;

    auto cpTile = [&](int stage, int k0) {
        __half* As = smf + stage * F2_STAGE;
        __half* Bs = As + F2_ABUF;
        #pragma unroll
        for (int i = 0; i < 2; i++) {
            int id = tid + i * 256;
            int m = id >> 3, c = (id & 7) << 3;
            cp16(As + m * F2_ASTR + c, g_th + (size_t)(m0 + m) * FFD + k0 + c);
        }
        #pragma unroll
        for (int i = 0; i < 4; i++) {
            int id = tid + i * 256;
            int k = id >> 4, c = (id & 15) << 3;
            cp16(Bs + k * F2_BSTR + c, g_W2h + (size_t)(k0 + k) * EDIM + c);
        }
    };

    uint32_t aoff[2];
    #pragma unroll
    for (int mt = 0; mt < 2; ++mt)
        aoff[mt] = (uint32_t)((wm * 32 + mt * 16 + (sel & 1) * 8 + lr) * F2_ASTR +
                              (sel >> 1) * 8);
    const uint32_t lm = (uint32_t)((lane & 15) * F2_BSTR + wn * 32 + ((lane >> 4) << 3));

    float acc[2][4][4];
    #pragma unroll
    for (int i = 0; i < 2; i++)
        #pragma unroll
        for (int j = 0; j < 4; j++)
            #pragma unroll
            for (int r = 0; r < 4; r++) acc[i][j][r] = 0.0f;

    cpTile(0, 0);
    cp_commit();

    for (int kt = 0; kt < 8; ++kt) {
        const int stage = kt & 1;
        if (kt + 1 < 8) { cpTile(stage ^ 1, (kt + 1) * 64); cp_commit(); cp_wait1(); }
        else            { cp_wait0(); }
        __syncthreads();
        const uint32_t abase = smb + 2u * (stage * F2_STAGE);
        const uint32_t bbase = smb + 2u * (stage * F2_STAGE + F2_ABUF + lm);
        #pragma unroll
        for (int ks = 0; ks < 4; ++ks) {
            const int kb = ks * 16;
            uint32_t a[2][4];
            #pragma unroll
            for (int mt = 0; mt < 2; ++mt)
                ldmx4(a[mt][0], a[mt][1], a[mt][2], a[mt][3],
                      abase + 2u * (aoff[mt] + kb));
            #pragma unroll
            for (int np = 0; np < 2; ++np) {
                uint32_t r0, r1, r2, r3;
                ldmx4t(r0, r1, r2, r3, bbase + 2u * (kb * F2_BSTR + np * 16));
                uint32_t b0[2] = {r0, r1}, b1r[2] = {r2, r3};
                mma_f16(acc[0][np * 2],     a[0], b0);
                mma_f16(acc[1][np * 2],     a[1], b0);
                mma_f16(acc[0][np * 2 + 1], a[0], b1r);
                mma_f16(acc[1][np * 2 + 1], a[1], b1r);
            }
        }
        __syncthreads();
    }

    #pragma unroll
    for (int mt = 0; mt < 2; ++mt) {
        #pragma unroll
        for (int nt = 0; nt < 4; ++nt) {
            const int col = wn * 32 + nt * 8 + tg * 2;
            const float bb0 = b2[col], bb1 = b2[col + 1];
            #pragma unroll
            for (int h = 0; h < 2; ++h) {
                const int row = m0 + wm * 32 + mt * 16 + g + h * 8;
                float v0 = acc[mt][nt][h * 2 + 0] + bb0 + res[(size_t)row * 128 + col];
                float v1 = acc[mt][nt][h * 2 + 1] + bb1 + res[(size_t)row * 128 + col + 1];
                out[(size_t)row * 128 + col]     = v0;
                out[(size_t)row * 128 + col + 1] = v1;
            }
        }
    }
}

// ---------------- launch ----------------
extern "C" void kernel_launch(void* const* d_in, const int* in_sizes, int n_in,
                              void* d_out, int out_size) {
    const float* x     = (const float*)d_in[0];
    const float* dis   = (const float*)d_in[1];
    const float* g_in  = (const float*)d_in[2];
    const float* g_po  = (const float*)d_in[3];
    const float* Wq    = (const float*)d_in[4];
    const float* Wk    = (const float*)d_in[5];
    const float* Wv    = (const float*)d_in[6];
    const float* alpha = (const float*)d_in[7];
    const float* Wo    = (const float*)d_in[8];
    const float* W1    = (const float*)d_in[9];
    const float* b1    = (const float*)d_in[10];
    const float* W2    = (const float*)d_in[11];
    const float* b2    = (const float*)d_in[12];
    float* out = (float*)d_out;

    float* p_out1;
    cudaGetSymbolAddress((void**)&p_out1, g_out1);

    cudaFuncSetAttribute(big_kernel,
                         cudaFuncAttributeMaxDynamicSharedMemorySize, BIG_SMEM);
    cudaFuncSetAttribute(qkv_kernel,
                         cudaFuncAttributeMaxDynamicSharedMemorySize, QKV_SMEM);
    cudaFuncSetAttribute(wo_norm_kernel,
                         cudaFuncAttributeMaxDynamicSharedMemorySize, WO_SMEM);
    cudaFuncSetAttribute(ff1_kernel,
                         cudaFuncAttributeMaxDynamicSharedMemorySize, F1_SMEM);
    cudaFuncSetAttribute(ff2_kernel,
                         cudaFuncAttributeMaxDynamicSharedMemorySize, F2_SMEM);

    prep_kernel<<<2304, 256>>>(x, g_in, W1, W2, Wo, Wq, Wk, Wv);
    qkv_kernel<<<dim3(NTOK / 128, 4), 256, QKV_SMEM>>>();
    big_kernel<<<dim3(NSEQ / 128, NB), 512, BIG_SMEM>>>(dis, alpha);
    wo_norm_kernel<<<NTOK / 64, 256, WO_SMEM>>>(x, g_po, p_out1);
    ff1_kernel<<<dim3(NTOK / 128, 8), 256, F1_SMEM>>>(b1);
    ff2_kernel<<<NTOK / 64, 256, F2_SMEM>>>(b2, p_out1, out);
}